// round 14
// baseline (speedup 1.0000x reference)
#include <cuda_runtime.h>
#include <cuda_fp16.h>
#include <stdint.h>
#include <math.h>

#define SEQ   1024
#define HDIM  2048
#define NH    16
#define KVH   8
#define HD    128
#define QKH   24
#define QKVO  4096
#define DFF   6144
#define VOC   32000
#define NLAY  2

#define L_QKV ((size_t)QKVO * HDIM)
#define L_O   ((size_t)HDIM * HDIM)
#define L_GU  ((size_t)2 * DFF * HDIM)
#define L_DN  ((size_t)HDIM * DFF)
#define L_ALL (L_QKV + L_O + L_GU + L_DN)

// ---------------- device scratch (no allocs allowed) ----------------
__device__ __align__(16) float g_x   [SEQ*HDIM];
__device__ __align__(16) half  g_hnf [SEQ*HDIM];
__device__ __align__(16) half  g_wall[2 * L_ALL];
__device__ __align__(16) float g_qkv [SEQ*QKVO];
__device__ __align__(16) half  g_qf  [NH*SEQ*HD];
__device__ __align__(16) half  g_kf  [KVH*SEQ*HD];
__device__ __align__(16) half  g_vtf [KVH*HD*SEQ];
__device__ __align__(16) half  g_scf [NH*SEQ*SEQ];
__device__ __align__(16) half  g_pf  [NH*SEQ*SEQ];
__device__ __align__(16) half  g_paof[SEQ*HDIM];
__device__ __align__(16) float g_gu  [SEQ*2*DFF];
__device__ __align__(16) half  g_actf[SEQ*DFF];
__device__ __align__(16) float g_last[HDIM];

// ---------------- helpers ----------------
__device__ __forceinline__ uint32_t smem_u32(const void* p) {
    uint32_t a;
    asm("{ .reg .u64 t; cvta.to.shared.u64 t, %1; cvt.u32.u64 %0, t; }" : "=r"(a) : "l"(p));
    return a;
}
__device__ __forceinline__ uint32_t pack2h(half a, half b) {
    return (uint32_t)__half_as_ushort(a) | ((uint32_t)__half_as_ushort(b) << 16);
}

#define CPA16(d, s) asm volatile("cp.async.cg.shared.global [%0], [%1], 16;" :: "r"(d), "l"(s))
#define CPA_COMMIT() asm volatile("cp.async.commit_group;" ::: "memory")
#define CPA_WAIT(n)  asm volatile("cp.async.wait_group %0;" :: "n"(n) : "memory")

#define LDSM4(r, a) \
    asm volatile("ldmatrix.sync.aligned.m8n8.x4.shared.b16 {%0,%1,%2,%3}, [%4];" \
        : "=r"((r)[0]), "=r"((r)[1]), "=r"((r)[2]), "=r"((r)[3]) : "r"(a))

#define MMA_F16(c, a, b0, b1) \
    asm volatile("mma.sync.aligned.m16n8k16.row.col.f32.f16.f16.f32 " \
        "{%0,%1,%2,%3}, {%4,%5,%6,%7}, {%8,%9}, {%0,%1,%2,%3};" \
        : "+f"((c)[0]), "+f"((c)[1]), "+f"((c)[2]), "+f"((c)[3]) \
        : "r"((a)[0]), "r"((a)[1]), "r"((a)[2]), "r"((a)[3]), "r"(b0), "r"(b1))

__device__ __forceinline__ uint2 cvt_f4(float4 v) {
    return make_uint2(pack2h(__float2half_rn(v.x), __float2half_rn(v.y)),
                      pack2h(__float2half_rn(v.z), __float2half_rn(v.w)));
}

// MLP=4 grid-stride converter
__device__ __forceinline__ void conv_range(const float4* __restrict__ src,
                                           uint2* __restrict__ dst, long long n4,
                                           long long cb, long long nblk, int tid)
{
    const long long stride = nblk * 256;
    long long i = cb * 256 + tid;
    for (; i + 3 * stride < n4; i += 4 * stride) {
        float4 a = src[i];
        float4 b = src[i + stride];
        float4 c = src[i + 2 * stride];
        float4 d = src[i + 3 * stride];
        dst[i]              = cvt_f4(a);
        dst[i + stride]     = cvt_f4(b);
        dst[i + 2 * stride] = cvt_f4(c);
        dst[i + 3 * stride] = cvt_f4(d);
    }
    for (; i < n4; i += stride) dst[i] = cvt_f4(src[i]);
}

// ============================================================================
// hgemm256: projection GEMM, 128(M) x 256(N) tile, warp tile 64x64, 8 warps,
// 3-stage cp.async (48KB stages), 1 CTA/SM. Hosted converter CTAs y>=nyG.
// ============================================================================
__global__ __launch_bounds__(256, 1)
void hgemm256(const half* __restrict__ A, int lda,
              const half* __restrict__ B, int ldb,
              float* __restrict__ Cf, half* __restrict__ Ch, int ldc, int K,
              const float* __restrict__ resid, int ldr,
              int nyG, const float4* __restrict__ cvsrc, uint2* __restrict__ cvdst,
              long long cvn4)
{
    const int tid = threadIdx.x;

    if ((int)blockIdx.y >= nyG) {
        const long long nblk = (long long)gridDim.x * (gridDim.y - nyG);
        const long long cb   = blockIdx.x + (long long)(blockIdx.y - nyG) * gridDim.x;
        conv_range(cvsrc, cvdst, cvn4, cb, nblk, tid);
        return;
    }

    constexpr int STG = 49152;       // A 16KB + B 32KB
    extern __shared__ char dynraw[];
    char* sm = (char*)(((uintptr_t)dynraw + 255) & ~(uintptr_t)255);
    const uint32_t smb = smem_u32(sm);

    const int m0 = blockIdx.x * 128;
    const int n0 = blockIdx.y * 256;
    const int lane = tid & 31;
    const int wid  = tid >> 5;
    const int wm   = (wid >> 2) * 64;     // 0 or 64
    const int wn   = (wid & 3) * 64;      // 0,64,128,192

    const int a_row_l  = lane & 15;
    const int a_colq_l = lane >> 4;
    const int b_row_l  = (lane & 7) + ((lane & 16) >> 1);
    const int b_colq_l = (lane >> 3) & 1;

    float acc[4][8][4];
#pragma unroll
    for (int i = 0; i < 4; i++)
#pragma unroll
        for (int j = 0; j < 8; j++)
#pragma unroll
            for (int q = 0; q < 4; q++) acc[i][j][q] = 0.f;

    auto load_chunk = [&](int c) {
        const int k0 = c << 6;
        const uint32_t st = smb + (c % 3) * STG;
#pragma unroll
        for (int it = 0; it < 4; it++) {          // A: 16KB
            const int g = it * 256 + tid;
            const int r = (g >> 3) & 127;
            const int q = g & 7;
            CPA16(st + r * 128 + ((q ^ (r & 7)) << 4),
                  A + (size_t)(m0 + r) * lda + k0 + q * 8);
        }
#pragma unroll
        for (int it = 0; it < 8; it++) {          // B: 32KB
            const int g = it * 256 + tid;
            const int r = (g >> 3) & 255;
            const int q = g & 7;
            CPA16(st + 16384 + r * 128 + ((q ^ (r & 7)) << 4),
                  B + (size_t)(n0 + r) * ldb + k0 + q * 8);
        }
        CPA_COMMIT();
    };

    const int nch = K >> 6;
    load_chunk(0);
    if (nch > 1) load_chunk(1);

    for (int c = 0; c < nch; c++) {
        if (c + 1 < nch) CPA_WAIT(1); else CPA_WAIT(0);
        __syncthreads();
        if (c + 2 < nch) load_chunk(c + 2);

        const uint32_t st = smb + (c % 3) * STG;
        const uint32_t sA = st, sB = st + 16384;

#pragma unroll
        for (int kk = 0; kk < 4; kk++) {
            uint32_t af[4][4];
            const int acq = kk * 2 + a_colq_l;
#pragma unroll
            for (int mi = 0; mi < 4; mi++) {
                const int r = wm + mi * 16 + a_row_l;
                LDSM4(af[mi], sA + r * 128 + ((acq ^ (r & 7)) << 4));
            }
            const int bcq = kk * 2 + b_colq_l;
#pragma unroll
            for (int nj = 0; nj < 4; nj++) {
                const int r = wn + nj * 16 + b_row_l;
                uint32_t t4[4];
                LDSM4(t4, sB + r * 128 + ((bcq ^ (r & 7)) << 4));
#pragma unroll
                for (int mi = 0; mi < 4; mi++) {
                    MMA_F16(acc[mi][nj * 2],     af[mi], t4[0], t4[1]);
                    MMA_F16(acc[mi][nj * 2 + 1], af[mi], t4[2], t4[3]);
                }
            }
        }
    }

    const int g = lane >> 2, t = lane & 3;
#pragma unroll
    for (int mi = 0; mi < 4; mi++)
#pragma unroll
        for (int ni = 0; ni < 8; ni++)
#pragma unroll
            for (int h2 = 0; h2 < 2; h2++) {
                const int row = m0 + wm + mi * 16 + g + h2 * 8;
                const int col = n0 + wn + ni * 8 + 2 * t;
                float v0 = acc[mi][ni][h2 * 2 + 0];
                float v1 = acc[mi][ni][h2 * 2 + 1];
                if (resid) {
                    const float* rp = resid + (size_t)row * ldr + col;
                    v0 += rp[0]; v1 += rp[1];
                }
                if (Cf) *(float2*)(Cf + (size_t)row * ldc + col) = make_float2(v0, v1);
                if (Ch)
                    *(uint32_t*)(Ch + (size_t)row * ldc + col) =
                        pack2h(__float2half_rn(v0), __float2half_rn(v1));
            }
}

// ============================================================================
// hgemm: 128x128 fp16 GEMM for attention (R8-proven), causal flags, batched z.
// ============================================================================
__global__ __launch_bounds__(256, 2)
void hgemm(const half* __restrict__ A, int lda,
           const half* __restrict__ B, int ldb,
           float* __restrict__ Cf, half* __restrict__ Ch, int ldc, int K,
           long long bsA, long long bsB, long long bsC, int bShiftB, int causal)
{
    constexpr int STG = 32768;
    extern __shared__ char dynraw[];
    char* sm = (char*)(((uintptr_t)dynraw + 255) & ~(uintptr_t)255);
    const uint32_t smb = smem_u32(sm);

    const int m0 = blockIdx.x * 128;
    const int n0 = blockIdx.y * 128;
    if ((causal & 1) && n0 > m0) return;

    const int tid  = threadIdx.x;
    const int lane = tid & 31;
    const int wid  = tid >> 5;
    const int wm   = (wid >> 2) * 64;
    const int wn   = (wid & 3) * 32;

    const long long z = blockIdx.z;
    A += z * bsA;
    B += (z >> bShiftB) * bsB;
    if (Cf) Cf += z * bsC;
    if (Ch) Ch += z * bsC;

    const int Keff = (causal & 2) ? min(K, m0 + 128) : K;
    const int nch  = Keff >> 6;

    const int a_row_l  = lane & 15;
    const int a_colq_l = lane >> 4;
    const int b_row_l  = (lane & 7) + ((lane & 16) >> 1);
    const int b_colq_l = (lane >> 3) & 1;

    float acc[4][4][4];
#pragma unroll
    for (int i = 0; i < 4; i++)
#pragma unroll
        for (int j = 0; j < 4; j++)
#pragma unroll
            for (int q = 0; q < 4; q++) acc[i][j][q] = 0.f;

    auto load_chunk = [&](int c) {
        const int k0 = c << 6;
        const uint32_t st = smb + (c % 3) * STG;
#pragma unroll
        for (int it = 0; it < 8; it++) {
            const int g   = it * 256 + tid;
            const int arr = it >> 2;
            const int r   = (g >> 3) & 127;
            const int q   = g & 7;
            const half* src = arr ? (B + (size_t)(n0 + r) * ldb + k0 + q * 8)
                                  : (A + (size_t)(m0 + r) * lda + k0 + q * 8);
            CPA16(st + arr * 16384 + r * 128 + ((q ^ (r & 7)) << 4), src);
        }
        CPA_COMMIT();
    };

    load_chunk(0);
    if (nch > 1) load_chunk(1);

    for (int c = 0; c < nch; c++) {
        if (c + 1 < nch) CPA_WAIT(1); else CPA_WAIT(0);
        __syncthreads();
        if (c + 2 < nch) load_chunk(c + 2);

        const uint32_t st = smb + (c % 3) * STG;
        const uint32_t sA = st, sB = st + 16384;

#pragma unroll
        for (int kk = 0; kk < 4; kk++) {
            uint32_t af[4][4], bfr[4][2];
            const int acq = kk * 2 + a_colq_l;
#pragma unroll
            for (int mi = 0; mi < 4; mi++) {
                const int r = wm + mi * 16 + a_row_l;
                LDSM4(af[mi], sA + r * 128 + ((acq ^ (r & 7)) << 4));
            }
            const int bcq = kk * 2 + b_colq_l;
#pragma unroll
            for (int nj = 0; nj < 2; nj++) {
                const int r = wn + nj * 16 + b_row_l;
                uint32_t t4[4];
                LDSM4(t4, sB + r * 128 + ((bcq ^ (r & 7)) << 4));
                bfr[nj*2][0] = t4[0]; bfr[nj*2][1] = t4[1];
                bfr[nj*2+1][0] = t4[2]; bfr[nj*2+1][1] = t4[3];
            }
#pragma unroll
            for (int mi = 0; mi < 4; mi++)
#pragma unroll
                for (int ni = 0; ni < 4; ni++)
                    MMA_F16(acc[mi][ni], af[mi], bfr[ni][0], bfr[ni][1]);
        }
    }

    const int g = lane >> 2, t = lane & 3;
#pragma unroll
    for (int mi = 0; mi < 4; mi++)
#pragma unroll
        for (int ni = 0; ni < 4; ni++)
#pragma unroll
            for (int h2 = 0; h2 < 2; h2++) {
                const int row = m0 + wm + mi * 16 + g + h2 * 8;
                const int col = n0 + wn + ni * 8 + 2 * t;
                float v0 = acc[mi][ni][h2 * 2 + 0];
                float v1 = acc[mi][ni][h2 * 2 + 1];
                if (Cf) *(float2*)(Cf + (size_t)row * ldc + col) = make_float2(v0, v1);
                if (Ch)
                    *(uint32_t*)(Ch + (size_t)row * ldc + col) =
                        pack2h(__float2half_rn(v0), __float2half_rn(v1));
            }
}

// ---------------- standalone fp32 -> fp16 convert (initial qkv-l0) ----------
__global__ void cvt4h(const float4* __restrict__ in, uint2* __restrict__ out, long long n4)
{
    long long i = (long long)blockIdx.x * blockDim.x + threadIdx.x;
    if (i >= n4) return;
    out[i] = cvt_f4(in[i]);
}

// ---------------- row l2norm -> fp16 ----------------
__global__ void l2norm_rows_h(const float* __restrict__ in, half* __restrict__ out, int cols)
{
    const int row = blockIdx.x;
    const float* x = in + (long long)row * cols;
    float s = 0.f;
    for (int c = threadIdx.x; c < cols; c += blockDim.x) { float v = x[c]; s += v * v; }
    __shared__ float red[32];
#pragma unroll
    for (int o = 16; o; o >>= 1) s += __shfl_xor_sync(0xffffffffu, s, o);
    if ((threadIdx.x & 31) == 0) red[threadIdx.x >> 5] = s;
    __syncthreads();
    const int nw = blockDim.x >> 5;
    if (threadIdx.x < 32) {
        float t = (threadIdx.x < nw) ? red[threadIdx.x] : 0.f;
#pragma unroll
        for (int o = 16; o; o >>= 1) t += __shfl_xor_sync(0xffffffffu, t, o);
        if (threadIdx.x == 0) red[0] = rsqrtf(t);
    }
    __syncthreads();
    const float r = red[0];
    for (int c = threadIdx.x; c < cols; c += blockDim.x)
        out[(long long)row * cols + c] = __float2half_rn(x[c] * r);
}

__global__ void l2norm_rows(const float* __restrict__ in, float* __restrict__ out, int cols)
{
    const int row = blockIdx.x;
    const float* x = in + (long long)row * cols;
    float* y = out + (long long)row * cols;
    float s = 0.f;
    for (int c = threadIdx.x; c < cols; c += blockDim.x) { float v = x[c]; s += v * v; }
    __shared__ float red[32];
#pragma unroll
    for (int o = 16; o; o >>= 1) s += __shfl_xor_sync(0xffffffffu, s, o);
    if ((threadIdx.x & 31) == 0) red[threadIdx.x >> 5] = s;
    __syncthreads();
    const int nw = blockDim.x >> 5;
    if (threadIdx.x < 32) {
        float t = (threadIdx.x < nw) ? red[threadIdx.x] : 0.f;
#pragma unroll
        for (int o = 16; o; o >>= 1) t += __shfl_xor_sync(0xffffffffu, t, o);
        if (threadIdx.x == 0) red[0] = rsqrtf(t);
    }
    __syncthreads();
    const float r = red[0];
    for (int c = threadIdx.x; c < cols; c += blockDim.x) y[c] = x[c] * r;
}

// ---------------- warp-per-head norm + RoPE -> fp16 Q/K ----------------
__global__ void qk_rope_w(const float* __restrict__ qkv, const float* __restrict__ qknw,
                          const float* __restrict__ cosb, const float* __restrict__ sinb,
                          half* __restrict__ Q, half* __restrict__ Kb)
{
    const int s    = blockIdx.x;
    const int lane = threadIdx.x & 31;
    const int warp = threadIdx.x >> 5;

#pragma unroll
    for (int hi = 0; hi < 3; hi++) {
        const int h = warp + hi * 8;
        const float* src = qkv + (size_t)s * QKVO + h * HD;
        float v[4];
        float ss = 0.f;
#pragma unroll
        for (int i = 0; i < 4; i++) {
            v[i] = src[i * 32 + lane];
            ss += v[i] * v[i];
        }
#pragma unroll
        for (int o = 16; o; o >>= 1) ss += __shfl_xor_sync(0xffffffffu, ss, o);
        const float r = rsqrtf(ss);
        float nv[4];
#pragma unroll
        for (int i = 0; i < 4; i++)
            nv[i] = v[i] * r * qknw[h * HD + i * 32 + lane];
        half ov[4];
#pragma unroll
        for (int i = 0; i < 4; i++) {
            const int d = i * 32 + lane;
            const float rot = nv[i ^ 2];
            ov[i] = __float2half_rn(nv[i] * cosb[s * HD + d] + rot * sinb[s * HD + d]);
        }
        half* dst = (h < NH) ? (Q + ((size_t)h * SEQ + s) * HD)
                             : (Kb + ((size_t)(h - NH) * SEQ + s) * HD);
#pragma unroll
        for (int i = 0; i < 4; i++) dst[i * 32 + lane] = ov[i];
    }
}

// ---------------- V transpose -> fp16 ----------------
__global__ void v_transpose_h(const float* __restrict__ qkv, half* __restrict__ Vt)
{
    __shared__ float t[32][33];
    const int h = blockIdx.z;
    const int s0 = blockIdx.x * 32;
    const int d0 = blockIdx.y * 32;
    t[threadIdx.y][threadIdx.x] =
        qkv[(long long)(s0 + threadIdx.y) * QKVO + QKH * HD + h * HD + d0 + threadIdx.x];
    __syncthreads();
    Vt[((size_t)h * HD + d0 + threadIdx.y) * SEQ + s0 + threadIdx.x] =
        __float2half_rn(t[threadIdx.x][threadIdx.y]);
}

// ---------------- causal softmax (fp16 in/out, K-limited) ----------------
__global__ void softmax_causal_h(const half* __restrict__ scores, const float* __restrict__ maskp,
                                 half* __restrict__ P)
{
    const int q = blockIdx.x;
    const int h = blockIdx.y;
    const int kmax = ((q >> 7) + 1) << 7;
    const half* row = scores + ((size_t)h * SEQ + q) * SEQ;
    const float mpen = -128.f * maskp[0];
    const int tid = threadIdx.x;

    float vals[4];
    float mx = -1e30f;
#pragma unroll
    for (int i = 0; i < 4; i++) {
        int k = tid + i * 256;
        if (k < kmax) {
            float v = __half2float(row[k]) + (k > q ? mpen : 0.f);
            vals[i] = v;
            mx = fmaxf(mx, v);
        } else vals[i] = -1e30f;
    }
    __shared__ float redm[8];
    __shared__ float reds[8];
#pragma unroll
    for (int o = 16; o; o >>= 1) mx = fmaxf(mx, __shfl_xor_sync(0xffffffffu, mx, o));
    if ((tid & 31) == 0) redm[tid >> 5] = mx;
    __syncthreads();
    if (tid < 32) {
        float m2 = (tid < 8) ? redm[tid] : -1e30f;
#pragma unroll
        for (int o = 16; o; o >>= 1) m2 = fmaxf(m2, __shfl_xor_sync(0xffffffffu, m2, o));
        if (tid == 0) redm[0] = m2;
    }
    __syncthreads();
    mx = redm[0];

    float s = 0.f;
#pragma unroll
    for (int i = 0; i < 4; i++) {
        int k = tid + i * 256;
        if (k < kmax) { vals[i] = expf(vals[i] - mx); s += vals[i]; }
    }
#pragma unroll
    for (int o = 16; o; o >>= 1) s += __shfl_xor_sync(0xffffffffu, s, o);
    if ((tid & 31) == 0) reds[tid >> 5] = s;
    __syncthreads();
    if (tid < 32) {
        float t2 = (tid < 8) ? reds[tid] : 0.f;
#pragma unroll
        for (int o = 16; o; o >>= 1) t2 += __shfl_xor_sync(0xffffffffu, t2, o);
        if (tid == 0) reds[0] = 1.f / t2;
    }
    __syncthreads();
    const float inv = reds[0];
    const size_t base = ((size_t)h * SEQ + q) * SEQ;
#pragma unroll
    for (int i = 0; i < 4; i++) {
        int k = tid + i * 256;
        if (k < kmax) P[base + k] = __float2half_rn(vals[i] * inv);
    }
}

// ---------------- SwiGLU -> fp16 (vectorized) ----------------
__global__ void silu_mul_h4(const float4* __restrict__ gu, uint2* __restrict__ act, int n4row)
{
    const long long i = (long long)blockIdx.x * blockDim.x + threadIdx.x;
    const int s  = (int)(i / n4row);
    const int f4 = (int)(i % n4row);
    const float4 g = gu[(size_t)s * (2 * n4row) + f4];
    const float4 u = gu[(size_t)s * (2 * n4row) + n4row + f4];
    float r0 = (g.x / (1.f + expf(-g.x))) * u.x;
    float r1 = (g.y / (1.f + expf(-g.y))) * u.y;
    float r2 = (g.z / (1.f + expf(-g.z))) * u.z;
    float r3 = (g.w / (1.f + expf(-g.w))) * u.w;
    act[i] = make_uint2(pack2h(__float2half_rn(r0), __float2half_rn(r1)),
                        pack2h(__float2half_rn(r2), __float2half_rn(r3)));
}

// ---------------- lm_head GEMV (fp32) ----------------
__global__ void lm_head(const float* __restrict__ last, const float* __restrict__ W,
                        float* __restrict__ out)
{
    const int warp = threadIdx.x >> 5;
    const int lane = threadIdx.x & 31;
    const int v = blockIdx.x * 8 + warp;
    const float* w = W + (long long)v * HDIM;
    float s = 0.f;
#pragma unroll
    for (int j = lane * 4; j < HDIM; j += 128) {
        float4 wv = *(const float4*)(w + j);
        float4 lv = *(const float4*)(last + j);
        s += wv.x * lv.x + wv.y * lv.y + wv.z * lv.z + wv.w * lv.w;
    }
#pragma unroll
    for (int o = 16; o; o >>= 1) s += __shfl_xor_sync(0xffffffffu, s, o);
    if (lane == 0) out[v] = s;
}

// ---------------- launcher ----------------
extern "C" void kernel_launch(void* const* d_in, const int* in_sizes, int n_in,
                              void* d_out, int out_size)
{
    const float* hidden = (const float*)d_in[0];
    const float* qkv_w  = (const float*)d_in[1];
    const float* qknw   = (const float*)d_in[2];
    const float* o_w    = (const float*)d_in[3];
    const float* gu_w   = (const float*)d_in[4];
    const float* dn_w   = (const float*)d_in[5];
    const float* lm_w   = (const float*)d_in[6];
    const float* cosb   = (const float*)d_in[7];
    const float* sinb   = (const float*)d_in[8];
    const float* maskp  = (const float*)d_in[9];
    float* outp = (float*)d_out;

    const int SMB  = 3 * 32768 + 256;   // attention kernel
    const int SMW  = 3 * 49152 + 256;   // hgemm256: 147712 -> 1 CTA/SM
    cudaFuncSetAttribute(hgemm,    cudaFuncAttributeMaxDynamicSharedMemorySize, SMB);
    cudaFuncSetAttribute(hgemm256, cudaFuncAttributeMaxDynamicSharedMemorySize, SMW);

    float *px, *pqkv, *pgu, *plast;
    half *phnf, *pwall, *pqf, *pkf, *pvtf, *pscf, *ppf, *ppaof, *pactf;
    cudaGetSymbolAddress((void**)&px,    g_x);
    cudaGetSymbolAddress((void**)&phnf,  g_hnf);
    cudaGetSymbolAddress((void**)&pwall, g_wall);
    cudaGetSymbolAddress((void**)&pqkv,  g_qkv);
    cudaGetSymbolAddress((void**)&pqf,   g_qf);
    cudaGetSymbolAddress((void**)&pkf,   g_kf);
    cudaGetSymbolAddress((void**)&pvtf,  g_vtf);
    cudaGetSymbolAddress((void**)&pscf,  g_scf);
    cudaGetSymbolAddress((void**)&ppf,   g_pf);
    cudaGetSymbolAddress((void**)&ppaof, g_paof);
    cudaGetSymbolAddress((void**)&pgu,   g_gu);
    cudaGetSymbolAddress((void**)&pactf, g_actf);
    cudaGetSymbolAddress((void**)&plast, g_last);

    half* w_qkv[2]; half* w_o[2]; half* w_gu[2]; half* w_dn[2];
    for (int l = 0; l < 2; l++) {
        half* base = pwall + (size_t)l * L_ALL;
        w_qkv[l] = base;
        w_o[l]   = base + L_QKV;
        w_gu[l]  = base + L_QKV + L_O;
        w_dn[l]  = base + L_QKV + L_O + L_GU;
    }

    // initial serial conversion: qkv weights, layer 0
    {
        long long n4 = (long long)(L_QKV / 4);
        cvt4h<<<(unsigned)((n4 + 255) / 256), 256>>>(
            (const float4*)qkv_w, (uint2*)w_qkv[0], n4);
    }

    const float* xin = hidden;

    for (int l = 0; l < NLAY; l++) {
        l2norm_rows_h<<<SEQ, 256>>>(xin, phnf, HDIM);

        // QKV projection (N=4096 -> 16 y-tiles); hosts o_w[l] (5 conv rows)
        hgemm256<<<dim3(SEQ / 128, QKVO / 256 + 5), 256, SMW>>>(
            phnf, HDIM, w_qkv[l], HDIM, pqkv, nullptr, QKVO, HDIM,
            nullptr, 0,
            QKVO / 256, (const float4*)(o_w + (size_t)l * L_O), (uint2*)w_o[l],
            (long long)(L_O / 4));

        qk_rope_w<<<SEQ, 256>>>(pqkv, qknw + (long long)l * QKH * HD, cosb, sinb, pqf, pkf);
        v_transpose_h<<<dim3(SEQ / 32, HD / 32, KVH), dim3(32, 32)>>>(pqkv, pvtf);

        // scores (causal tile skip)
        hgemm<<<dim3(SEQ / 128, SEQ / 128, NH), 256, SMB>>>(
            pqf, HD, pkf, HD, nullptr, pscf, SEQ, HD,
            (long long)SEQ * HD, (long long)SEQ * HD, (long long)SEQ * SEQ, 1, 1);

        softmax_causal_h<<<dim3(SEQ, NH), 256>>>(pscf, maskp, ppf);

        // PV (K-limited)
        hgemm<<<dim3(SEQ / 128, 1, NH), 256, SMB>>>(
            ppf, SEQ, pvtf, SEQ, nullptr, ppaof, HDIM, SEQ,
            (long long)SEQ * SEQ, (long long)HD * SEQ, (long long)HD, 1, 2);

        // O projection + residual (N=2048 -> 8 y-tiles); hosts gu_w[l] (13 conv rows)
        hgemm256<<<dim3(SEQ / 128, HDIM / 256 + 13), 256, SMW>>>(
            ppaof, HDIM, w_o[l], HDIM, px, nullptr, HDIM, HDIM,
            xin, HDIM,
            HDIM / 256, (const float4*)(gu_w + (size_t)l * L_GU), (uint2*)w_gu[l],
            (long long)(L_GU / 4));

        // MLP
        l2norm_rows_h<<<SEQ, 256>>>(px, phnf, HDIM);

        // gate_up (N=12288 -> 48 y-tiles); hosts dn_w[l] (8 conv rows)
        hgemm256<<<dim3(SEQ / 128, 2 * DFF / 256 + 8), 256, SMW>>>(
            phnf, HDIM, w_gu[l], HDIM, pgu, nullptr, 2 * DFF, HDIM,
            nullptr, 0,
            2 * DFF / 256, (const float4*)(dn_w + (size_t)l * L_DN), (uint2*)w_dn[l],
            (long long)(L_DN / 4));

        silu_mul_h4<<<(SEQ * DFF / 4) / 256, 256>>>((const float4*)pgu, (uint2*)pactf, DFF / 4);

        // down (N=2048 -> 8 y-tiles); hosts next layer's qkv_w (13 conv rows)
        const int lastL = (l == NLAY - 1);
        hgemm256<<<dim3(SEQ / 128, HDIM / 256 + (lastL ? 0 : 13)), 256, SMW>>>(
            pactf, DFF, w_dn[l], DFF, px, nullptr, HDIM, DFF,
            px, HDIM,
            HDIM / 256,
            lastL ? nullptr : (const float4*)(qkv_w + (size_t)(l + 1) * L_QKV),
            lastL ? nullptr : (uint2*)w_qkv[l + 1],
            lastL ? 0 : (long long)(L_QKV / 4));

        xin = px;
    }

    l2norm_rows<<<1, 256>>>(px + (long long)(SEQ - 1) * HDIM, plast, HDIM);
    lm_head<<<VOC / 8, 256>>>(plast, lm_w, outp);
}

// round 15
// speedup vs baseline: 1.2183x; 1.2183x over previous
#include <cuda_runtime.h>
#include <cuda_fp16.h>
#include <stdint.h>
#include <math.h>

#define SEQ   1024
#define HDIM  2048
#define NH    16
#define KVH   8
#define HD    128
#define QKH   24
#define QKVO  4096
#define DFF   6144
#define VOC   32000
#define NLAY  2

#define L_QKV ((size_t)QKVO * HDIM)
#define L_O   ((size_t)HDIM * HDIM)
#define L_GU  ((size_t)2 * DFF * HDIM)
#define L_DN  ((size_t)HDIM * DFF)
#define L_ALL (L_QKV + L_O + L_GU + L_DN)

// ---------------- device scratch (no allocs allowed) ----------------
__device__ __align__(16) float g_x   [SEQ*HDIM];
__device__ __align__(16) half  g_hnf [SEQ*HDIM];
__device__ __align__(16) half  g_wall[2 * L_ALL];
__device__ __align__(16) float g_qkv [SEQ*QKVO];
__device__ __align__(16) half  g_qf  [NH*SEQ*HD];
__device__ __align__(16) half  g_kf  [KVH*SEQ*HD];
__device__ __align__(16) half  g_vtf [KVH*HD*SEQ];
__device__ __align__(16) half  g_scf [NH*SEQ*SEQ];
__device__ __align__(16) half  g_pf  [NH*SEQ*SEQ];
__device__ __align__(16) half  g_paof[SEQ*HDIM];
__device__ __align__(16) float g_gu  [SEQ*2*DFF];
__device__ __align__(16) half  g_actf[SEQ*DFF];
__device__ __align__(16) float g_last[HDIM];

// ---------------- helpers ----------------
__device__ __forceinline__ uint32_t smem_u32(const void* p) {
    uint32_t a;
    asm("{ .reg .u64 t; cvta.to.shared.u64 t, %1; cvt.u32.u64 %0, t; }" : "=r"(a) : "l"(p));
    return a;
}
__device__ __forceinline__ uint32_t pack2h(half a, half b) {
    return (uint32_t)__half_as_ushort(a) | ((uint32_t)__half_as_ushort(b) << 16);
}

#define CPA16(d, s) asm volatile("cp.async.cg.shared.global [%0], [%1], 16;" :: "r"(d), "l"(s))
#define CPA_COMMIT() asm volatile("cp.async.commit_group;" ::: "memory")
#define CPA_WAIT(n)  asm volatile("cp.async.wait_group %0;" :: "n"(n) : "memory")

#define LDSM4(r, a) \
    asm volatile("ldmatrix.sync.aligned.m8n8.x4.shared.b16 {%0,%1,%2,%3}, [%4];" \
        : "=r"((r)[0]), "=r"((r)[1]), "=r"((r)[2]), "=r"((r)[3]) : "r"(a))

#define MMA_F16(c, a, b0, b1) \
    asm volatile("mma.sync.aligned.m16n8k16.row.col.f32.f16.f16.f32 " \
        "{%0,%1,%2,%3}, {%4,%5,%6,%7}, {%8,%9}, {%0,%1,%2,%3};" \
        : "+f"((c)[0]), "+f"((c)[1]), "+f"((c)[2]), "+f"((c)[3]) \
        : "r"((a)[0]), "r"((a)[1]), "r"((a)[2]), "r"((a)[3]), "r"(b0), "r"(b1))

__device__ __forceinline__ uint2 cvt_f4(float4 v) {
    return make_uint2(pack2h(__float2half_rn(v.x), __float2half_rn(v.y)),
                      pack2h(__float2half_rn(v.z), __float2half_rn(v.w)));
}

// MLP=4 grid-stride converter
__device__ __forceinline__ void conv_range(const float4* __restrict__ src,
                                           uint2* __restrict__ dst, long long n4,
                                           long long cb, long long nblk, int tid)
{
    const long long stride = nblk * 256;
    long long i = cb * 256 + tid;
    for (; i + 3 * stride < n4; i += 4 * stride) {
        float4 a = src[i];
        float4 b = src[i + stride];
        float4 c = src[i + 2 * stride];
        float4 d = src[i + 3 * stride];
        dst[i]              = cvt_f4(a);
        dst[i + stride]     = cvt_f4(b);
        dst[i + 2 * stride] = cvt_f4(c);
        dst[i + 3 * stride] = cvt_f4(d);
    }
    for (; i < n4; i += stride) dst[i] = cvt_f4(src[i]);
}

// ============================================================================
// hgemm: 128x128 fp16 GEMM (R13-proven) + hosted converter CTAs (y>=nyG,z==0).
// causal bit0: skip n0>m0 tiles. bit1: K-limit to m0+128.
// ============================================================================
__global__ __launch_bounds__(256, 2)
void hgemm(const half* __restrict__ A, int lda,
           const half* __restrict__ B, int ldb,
           float* __restrict__ Cf, half* __restrict__ Ch, int ldc, int K,
           const float* __restrict__ resid, int ldr,
           long long bsA, long long bsB, long long bsC, int bShiftB, int causal,
           int nyG, const float4* __restrict__ cvsrc, uint2* __restrict__ cvdst,
           long long cvn4)
{
    const int tid = threadIdx.x;

    if ((int)blockIdx.y >= nyG) {
        if (blockIdx.z != 0) return;
        const long long nblk = (long long)gridDim.x * (gridDim.y - nyG);
        const long long cb   = blockIdx.x + (long long)(blockIdx.y - nyG) * gridDim.x;
        conv_range(cvsrc, cvdst, cvn4, cb, nblk, tid);
        return;
    }

    constexpr int STG = 32768;
    extern __shared__ char dynraw[];
    char* sm = (char*)(((uintptr_t)dynraw + 255) & ~(uintptr_t)255);
    const uint32_t smb = smem_u32(sm);

    const int m0 = blockIdx.x * 128;
    const int n0 = blockIdx.y * 128;
    if ((causal & 1) && n0 > m0) return;

    const int lane = tid & 31;
    const int wid  = tid >> 5;
    const int wm   = (wid >> 2) * 64;
    const int wn   = (wid & 3) * 32;

    const long long z = blockIdx.z;
    A += z * bsA;
    B += (z >> bShiftB) * bsB;
    if (Cf) Cf += z * bsC;
    if (Ch) Ch += z * bsC;

    const int Keff = (causal & 2) ? min(K, m0 + 128) : K;
    const int nch  = Keff >> 6;

    const int a_row_l  = lane & 15;
    const int a_colq_l = lane >> 4;
    const int b_row_l  = (lane & 7) + ((lane & 16) >> 1);
    const int b_colq_l = (lane >> 3) & 1;

    float acc[4][4][4];
#pragma unroll
    for (int i = 0; i < 4; i++)
#pragma unroll
        for (int j = 0; j < 4; j++)
#pragma unroll
            for (int q = 0; q < 4; q++) acc[i][j][q] = 0.f;

    auto load_chunk = [&](int c) {
        const int k0 = c << 6;
        const uint32_t st = smb + (c % 3) * STG;
#pragma unroll
        for (int it = 0; it < 8; it++) {
            const int g   = it * 256 + tid;
            const int arr = it >> 2;
            const int r   = (g >> 3) & 127;
            const int q   = g & 7;
            const half* src = arr ? (B + (size_t)(n0 + r) * ldb + k0 + q * 8)
                                  : (A + (size_t)(m0 + r) * lda + k0 + q * 8);
            CPA16(st + arr * 16384 + r * 128 + ((q ^ (r & 7)) << 4), src);
        }
        CPA_COMMIT();
    };

    load_chunk(0);
    if (nch > 1) load_chunk(1);

    for (int c = 0; c < nch; c++) {
        if (c + 1 < nch) CPA_WAIT(1); else CPA_WAIT(0);
        __syncthreads();
        if (c + 2 < nch) load_chunk(c + 2);

        const uint32_t st = smb + (c % 3) * STG;
        const uint32_t sA = st, sB = st + 16384;

#pragma unroll
        for (int kk = 0; kk < 4; kk++) {
            uint32_t af[4][4], bfr[4][2];
            const int acq = kk * 2 + a_colq_l;
#pragma unroll
            for (int mi = 0; mi < 4; mi++) {
                const int r = wm + mi * 16 + a_row_l;
                LDSM4(af[mi], sA + r * 128 + ((acq ^ (r & 7)) << 4));
            }
            const int bcq = kk * 2 + b_colq_l;
#pragma unroll
            for (int nj = 0; nj < 2; nj++) {
                const int r = wn + nj * 16 + b_row_l;
                uint32_t t4[4];
                LDSM4(t4, sB + r * 128 + ((bcq ^ (r & 7)) << 4));
                bfr[nj*2][0] = t4[0]; bfr[nj*2][1] = t4[1];
                bfr[nj*2+1][0] = t4[2]; bfr[nj*2+1][1] = t4[3];
            }
#pragma unroll
            for (int mi = 0; mi < 4; mi++)
#pragma unroll
                for (int ni = 0; ni < 4; ni++)
                    MMA_F16(acc[mi][ni], af[mi], bfr[ni][0], bfr[ni][1]);
        }
    }

    const int g = lane >> 2, t = lane & 3;
#pragma unroll
    for (int mi = 0; mi < 4; mi++)
#pragma unroll
        for (int ni = 0; ni < 4; ni++)
#pragma unroll
            for (int h2 = 0; h2 < 2; h2++) {
                const int row = m0 + wm + mi * 16 + g + h2 * 8;
                const int col = n0 + wn + ni * 8 + 2 * t;
                float v0 = acc[mi][ni][h2 * 2 + 0];
                float v1 = acc[mi][ni][h2 * 2 + 1];
                if (resid) {
                    const float* rp = resid + (size_t)row * ldr + col;
                    v0 += rp[0]; v1 += rp[1];
                }
                if (Cf) *(float2*)(Cf + (size_t)row * ldc + col) = make_float2(v0, v1);
                if (Ch)
                    *(uint32_t*)(Ch + (size_t)row * ldc + col) =
                        pack2h(__float2half_rn(v0), __float2half_rn(v1));
            }
}

// ============================================================================
// hgemm64: 64(M)x128(N) tile, warp tile 32x32, for under-occupied o/down GEMMs.
// 24KB stages x3, 2 CTAs/SM. Hosted converter CTAs y>=nyG.
// ============================================================================
__global__ __launch_bounds__(256, 2)
void hgemm64(const half* __restrict__ A, int lda,
             const half* __restrict__ B, int ldb,
             float* __restrict__ Cf, half* __restrict__ Ch, int ldc, int K,
             const float* __restrict__ resid, int ldr,
             int nyG, const float4* __restrict__ cvsrc, uint2* __restrict__ cvdst,
             long long cvn4)
{
    const int tid = threadIdx.x;

    if ((int)blockIdx.y >= nyG) {
        const long long nblk = (long long)gridDim.x * (gridDim.y - nyG);
        const long long cb   = blockIdx.x + (long long)(blockIdx.y - nyG) * gridDim.x;
        conv_range(cvsrc, cvdst, cvn4, cb, nblk, tid);
        return;
    }

    constexpr int STG = 24576;    // A 8KB + B 16KB
    extern __shared__ char dynraw[];
    char* sm = (char*)(((uintptr_t)dynraw + 255) & ~(uintptr_t)255);
    const uint32_t smb = smem_u32(sm);

    const int m0 = blockIdx.x * 64;
    const int n0 = blockIdx.y * 128;
    const int lane = tid & 31;
    const int wid  = tid >> 5;
    const int wm   = (wid >> 2) * 32;     // 0 or 32
    const int wn   = (wid & 3) * 32;

    const int a_row_l  = lane & 15;
    const int a_colq_l = lane >> 4;
    const int b_row_l  = (lane & 7) + ((lane & 16) >> 1);
    const int b_colq_l = (lane >> 3) & 1;

    float acc[2][4][4];
#pragma unroll
    for (int i = 0; i < 2; i++)
#pragma unroll
        for (int j = 0; j < 4; j++)
#pragma unroll
            for (int q = 0; q < 4; q++) acc[i][j][q] = 0.f;

    auto load_chunk = [&](int c) {
        const int k0 = c << 6;
        const uint32_t st = smb + (c % 3) * STG;
#pragma unroll
        for (int it = 0; it < 2; it++) {          // A: 8KB (64 rows)
            const int g = it * 256 + tid;
            const int r = (g >> 3) & 63;
            const int q = g & 7;
            CPA16(st + r * 128 + ((q ^ (r & 7)) << 4),
                  A + (size_t)(m0 + r) * lda + k0 + q * 8);
        }
#pragma unroll
        for (int it = 0; it < 4; it++) {          // B: 16KB (128 rows)
            const int g = it * 256 + tid;
            const int r = (g >> 3) & 127;
            const int q = g & 7;
            CPA16(st + 8192 + r * 128 + ((q ^ (r & 7)) << 4),
                  B + (size_t)(n0 + r) * ldb + k0 + q * 8);
        }
        CPA_COMMIT();
    };

    const int nch = K >> 6;
    load_chunk(0);
    if (nch > 1) load_chunk(1);

    for (int c = 0; c < nch; c++) {
        if (c + 1 < nch) CPA_WAIT(1); else CPA_WAIT(0);
        __syncthreads();
        if (c + 2 < nch) load_chunk(c + 2);

        const uint32_t st = smb + (c % 3) * STG;
        const uint32_t sA = st, sB = st + 8192;

#pragma unroll
        for (int kk = 0; kk < 4; kk++) {
            uint32_t af[2][4], bfr[4][2];
            const int acq = kk * 2 + a_colq_l;
#pragma unroll
            for (int mi = 0; mi < 2; mi++) {
                const int r = wm + mi * 16 + a_row_l;
                LDSM4(af[mi], sA + r * 128 + ((acq ^ (r & 7)) << 4));
            }
            const int bcq = kk * 2 + b_colq_l;
#pragma unroll
            for (int nj = 0; nj < 2; nj++) {
                const int r = wn + nj * 16 + b_row_l;
                uint32_t t4[4];
                LDSM4(t4, sB + r * 128 + ((bcq ^ (r & 7)) << 4));
                bfr[nj*2][0] = t4[0]; bfr[nj*2][1] = t4[1];
                bfr[nj*2+1][0] = t4[2]; bfr[nj*2+1][1] = t4[3];
            }
#pragma unroll
            for (int mi = 0; mi < 2; mi++)
#pragma unroll
                for (int ni = 0; ni < 4; ni++)
                    MMA_F16(acc[mi][ni], af[mi], bfr[ni][0], bfr[ni][1]);
        }
    }

    const int g = lane >> 2, t = lane & 3;
#pragma unroll
    for (int mi = 0; mi < 2; mi++)
#pragma unroll
        for (int ni = 0; ni < 4; ni++)
#pragma unroll
            for (int h2 = 0; h2 < 2; h2++) {
                const int row = m0 + wm + mi * 16 + g + h2 * 8;
                const int col = n0 + wn + ni * 8 + 2 * t;
                float v0 = acc[mi][ni][h2 * 2 + 0];
                float v1 = acc[mi][ni][h2 * 2 + 1];
                if (resid) {
                    const float* rp = resid + (size_t)row * ldr + col;
                    v0 += rp[0]; v1 += rp[1];
                }
                if (Cf) *(float2*)(Cf + (size_t)row * ldc + col) = make_float2(v0, v1);
                if (Ch)
                    *(uint32_t*)(Ch + (size_t)row * ldc + col) =
                        pack2h(__float2half_rn(v0), __float2half_rn(v1));
            }
}

// ---------------- standalone fp32 -> fp16 convert (initial qkv-l0) ----------
__global__ void cvt4h(const float4* __restrict__ in, uint2* __restrict__ out, long long n4)
{
    long long i = (long long)blockIdx.x * blockDim.x + threadIdx.x;
    if (i >= n4) return;
    out[i] = cvt_f4(in[i]);
}

// ---------------- row l2norm -> fp16 ----------------
__global__ void l2norm_rows_h(const float* __restrict__ in, half* __restrict__ out, int cols)
{
    const int row = blockIdx.x;
    const float* x = in + (long long)row * cols;
    float s = 0.f;
    for (int c = threadIdx.x; c < cols; c += blockDim.x) { float v = x[c]; s += v * v; }
    __shared__ float red[32];
#pragma unroll
    for (int o = 16; o; o >>= 1) s += __shfl_xor_sync(0xffffffffu, s, o);
    if ((threadIdx.x & 31) == 0) red[threadIdx.x >> 5] = s;
    __syncthreads();
    const int nw = blockDim.x >> 5;
    if (threadIdx.x < 32) {
        float t = (threadIdx.x < nw) ? red[threadIdx.x] : 0.f;
#pragma unroll
        for (int o = 16; o; o >>= 1) t += __shfl_xor_sync(0xffffffffu, t, o);
        if (threadIdx.x == 0) red[0] = rsqrtf(t);
    }
    __syncthreads();
    const float r = red[0];
    for (int c = threadIdx.x; c < cols; c += blockDim.x)
        out[(long long)row * cols + c] = __float2half_rn(x[c] * r);
}

__global__ void l2norm_rows(const float* __restrict__ in, float* __restrict__ out, int cols)
{
    const int row = blockIdx.x;
    const float* x = in + (long long)row * cols;
    float* y = out + (long long)row * cols;
    float s = 0.f;
    for (int c = threadIdx.x; c < cols; c += blockDim.x) { float v = x[c]; s += v * v; }
    __shared__ float red[32];
#pragma unroll
    for (int o = 16; o; o >>= 1) s += __shfl_xor_sync(0xffffffffu, s, o);
    if ((threadIdx.x & 31) == 0) red[threadIdx.x >> 5] = s;
    __syncthreads();
    const int nw = blockDim.x >> 5;
    if (threadIdx.x < 32) {
        float t = (threadIdx.x < nw) ? red[threadIdx.x] : 0.f;
#pragma unroll
        for (int o = 16; o; o >>= 1) t += __shfl_xor_sync(0xffffffffu, t, o);
        if (threadIdx.x == 0) red[0] = rsqrtf(t);
    }
    __syncthreads();
    const float r = red[0];
    for (int c = threadIdx.x; c < cols; c += blockDim.x) y[c] = x[c] * r;
}

// ---------------- warp-per-head norm + RoPE -> fp16 Q/K ----------------
__global__ void qk_rope_w(const float* __restrict__ qkv, const float* __restrict__ qknw,
                          const float* __restrict__ cosb, const float* __restrict__ sinb,
                          half* __restrict__ Q, half* __restrict__ Kb)
{
    const int s    = blockIdx.x;
    const int lane = threadIdx.x & 31;
    const int warp = threadIdx.x >> 5;

#pragma unroll
    for (int hi = 0; hi < 3; hi++) {
        const int h = warp + hi * 8;
        const float* src = qkv + (size_t)s * QKVO + h * HD;
        float v[4];
        float ss = 0.f;
#pragma unroll
        for (int i = 0; i < 4; i++) {
            v[i] = src[i * 32 + lane];
            ss += v[i] * v[i];
        }
#pragma unroll
        for (int o = 16; o; o >>= 1) ss += __shfl_xor_sync(0xffffffffu, ss, o);
        const float r = rsqrtf(ss);
        float nv[4];
#pragma unroll
        for (int i = 0; i < 4; i++)
            nv[i] = v[i] * r * qknw[h * HD + i * 32 + lane];
        half ov[4];
#pragma unroll
        for (int i = 0; i < 4; i++) {
            const int d = i * 32 + lane;
            const float rot = nv[i ^ 2];
            ov[i] = __float2half_rn(nv[i] * cosb[s * HD + d] + rot * sinb[s * HD + d]);
        }
        half* dst = (h < NH) ? (Q + ((size_t)h * SEQ + s) * HD)
                             : (Kb + ((size_t)(h - NH) * SEQ + s) * HD);
#pragma unroll
        for (int i = 0; i < 4; i++) dst[i * 32 + lane] = ov[i];
    }
}

// ---------------- V transpose -> fp16 ----------------
__global__ void v_transpose_h(const float* __restrict__ qkv, half* __restrict__ Vt)
{
    __shared__ float t[32][33];
    const int h = blockIdx.z;
    const int s0 = blockIdx.x * 32;
    const int d0 = blockIdx.y * 32;
    t[threadIdx.y][threadIdx.x] =
        qkv[(long long)(s0 + threadIdx.y) * QKVO + QKH * HD + h * HD + d0 + threadIdx.x];
    __syncthreads();
    Vt[((size_t)h * HD + d0 + threadIdx.y) * SEQ + s0 + threadIdx.x] =
        __float2half_rn(t[threadIdx.x][threadIdx.y]);
}

// ---------------- causal softmax (fp16 in/out, K-limited) ----------------
__global__ void softmax_causal_h(const half* __restrict__ scores, const float* __restrict__ maskp,
                                 half* __restrict__ P)
{
    const int q = blockIdx.x;
    const int h = blockIdx.y;
    const int kmax = ((q >> 7) + 1) << 7;
    const half* row = scores + ((size_t)h * SEQ + q) * SEQ;
    const float mpen = -128.f * maskp[0];
    const int tid = threadIdx.x;

    float vals[4];
    float mx = -1e30f;
#pragma unroll
    for (int i = 0; i < 4; i++) {
        int k = tid + i * 256;
        if (k < kmax) {
            float v = __half2float(row[k]) + (k > q ? mpen : 0.f);
            vals[i] = v;
            mx = fmaxf(mx, v);
        } else vals[i] = -1e30f;
    }
    __shared__ float redm[8];
    __shared__ float reds[8];
#pragma unroll
    for (int o = 16; o; o >>= 1) mx = fmaxf(mx, __shfl_xor_sync(0xffffffffu, mx, o));
    if ((tid & 31) == 0) redm[tid >> 5] = mx;
    __syncthreads();
    if (tid < 32) {
        float m2 = (tid < 8) ? redm[tid] : -1e30f;
#pragma unroll
        for (int o = 16; o; o >>= 1) m2 = fmaxf(m2, __shfl_xor_sync(0xffffffffu, m2, o));
        if (tid == 0) redm[0] = m2;
    }
    __syncthreads();
    mx = redm[0];

    float s = 0.f;
#pragma unroll
    for (int i = 0; i < 4; i++) {
        int k = tid + i * 256;
        if (k < kmax) { vals[i] = expf(vals[i] - mx); s += vals[i]; }
    }
#pragma unroll
    for (int o = 16; o; o >>= 1) s += __shfl_xor_sync(0xffffffffu, s, o);
    if ((tid & 31) == 0) reds[tid >> 5] = s;
    __syncthreads();
    if (tid < 32) {
        float t2 = (tid < 8) ? reds[tid] : 0.f;
#pragma unroll
        for (int o = 16; o; o >>= 1) t2 += __shfl_xor_sync(0xffffffffu, t2, o);
        if (tid == 0) reds[0] = 1.f / t2;
    }
    __syncthreads();
    const float inv = reds[0];
    const size_t base = ((size_t)h * SEQ + q) * SEQ;
#pragma unroll
    for (int i = 0; i < 4; i++) {
        int k = tid + i * 256;
        if (k < kmax) P[base + k] = __float2half_rn(vals[i] * inv);
    }
}

// ---------------- SwiGLU -> fp16 (vectorized) ----------------
__global__ void silu_mul_h4(const float4* __restrict__ gu, uint2* __restrict__ act, int n4row)
{
    const long long i = (long long)blockIdx.x * blockDim.x + threadIdx.x;
    const int s  = (int)(i / n4row);
    const int f4 = (int)(i % n4row);
    const float4 g = gu[(size_t)s * (2 * n4row) + f4];
    const float4 u = gu[(size_t)s * (2 * n4row) + n4row + f4];
    float r0 = (g.x / (1.f + expf(-g.x))) * u.x;
    float r1 = (g.y / (1.f + expf(-g.y))) * u.y;
    float r2 = (g.z / (1.f + expf(-g.z))) * u.z;
    float r3 = (g.w / (1.f + expf(-g.w))) * u.w;
    act[i] = make_uint2(pack2h(__float2half_rn(r0), __float2half_rn(r1)),
                        pack2h(__float2half_rn(r2), __float2half_rn(r3)));
}

// ---------------- lm_head GEMV (fp32) ----------------
__global__ void lm_head(const float* __restrict__ last, const float* __restrict__ W,
                        float* __restrict__ out)
{
    const int warp = threadIdx.x >> 5;
    const int lane = threadIdx.x & 31;
    const int v = blockIdx.x * 8 + warp;
    const float* w = W + (long long)v * HDIM;
    float s = 0.f;
#pragma unroll
    for (int j = lane * 4; j < HDIM; j += 128) {
        float4 wv = *(const float4*)(w + j);
        float4 lv = *(const float4*)(last + j);
        s += wv.x * lv.x + wv.y * lv.y + wv.z * lv.z + wv.w * lv.w;
    }
#pragma unroll
    for (int o = 16; o; o >>= 1) s += __shfl_xor_sync(0xffffffffu, s, o);
    if (lane == 0) out[v] = s;
}

// ---------------- launcher ----------------
extern "C" void kernel_launch(void* const* d_in, const int* in_sizes, int n_in,
                              void* d_out, int out_size)
{
    const float* hidden = (const float*)d_in[0];
    const float* qkv_w  = (const float*)d_in[1];
    const float* qknw   = (const float*)d_in[2];
    const float* o_w    = (const float*)d_in[3];
    const float* gu_w   = (const float*)d_in[4];
    const float* dn_w   = (const float*)d_in[5];
    const float* lm_w   = (const float*)d_in[6];
    const float* cosb   = (const float*)d_in[7];
    const float* sinb   = (const float*)d_in[8];
    const float* maskp  = (const float*)d_in[9];
    float* outp = (float*)d_out;

    const int SMB  = 3 * 32768 + 256;   // hgemm: 98560 -> 2 CTAs/SM
    const int SM64 = 3 * 24576 + 256;   // hgemm64: 73984 -> 2 CTAs/SM
    cudaFuncSetAttribute(hgemm,   cudaFuncAttributeMaxDynamicSharedMemorySize, SMB);
    cudaFuncSetAttribute(hgemm64, cudaFuncAttributeMaxDynamicSharedMemorySize, SM64);

    float *px, *pqkv, *pgu, *plast;
    half *phnf, *pwall, *pqf, *pkf, *pvtf, *pscf, *ppf, *ppaof, *pactf;
    cudaGetSymbolAddress((void**)&px,    g_x);
    cudaGetSymbolAddress((void**)&phnf,  g_hnf);
    cudaGetSymbolAddress((void**)&pwall, g_wall);
    cudaGetSymbolAddress((void**)&pqkv,  g_qkv);
    cudaGetSymbolAddress((void**)&pqf,   g_qf);
    cudaGetSymbolAddress((void**)&pkf,   g_kf);
    cudaGetSymbolAddress((void**)&pvtf,  g_vtf);
    cudaGetSymbolAddress((void**)&pscf,  g_scf);
    cudaGetSymbolAddress((void**)&ppf,   g_pf);
    cudaGetSymbolAddress((void**)&ppaof, g_paof);
    cudaGetSymbolAddress((void**)&pgu,   g_gu);
    cudaGetSymbolAddress((void**)&pactf, g_actf);
    cudaGetSymbolAddress((void**)&plast, g_last);

    half* w_qkv[2]; half* w_o[2]; half* w_gu[2]; half* w_dn[2];
    for (int l = 0; l < 2; l++) {
        half* base = pwall + (size_t)l * L_ALL;
        w_qkv[l] = base;
        w_o[l]   = base + L_QKV;
        w_gu[l]  = base + L_QKV + L_O;
        w_dn[l]  = base + L_QKV + L_O + L_GU;
    }

    // initial serial conversion: qkv weights, layer 0
    {
        long long n4 = (long long)(L_QKV / 4);
        cvt4h<<<(unsigned)((n4 + 255) / 256), 256>>>(
            (const float4*)qkv_w, (uint2*)w_qkv[0], n4);
    }

    const float* xin = hidden;

    for (int l = 0; l < NLAY; l++) {
        l2norm_rows_h<<<SEQ, 256>>>(xin, phnf, HDIM);

        // QKV projection; hosts o_w[l] (32 GEMM + 5 conv rows)
        hgemm<<<dim3(SEQ / 128, QKVO / 128 + 5, 1), 256, SMB>>>(
            phnf, HDIM, w_qkv[l], HDIM, pqkv, nullptr, QKVO, HDIM,
            nullptr, 0, 0, 0, 0, 0, 0,
            QKVO / 128, (const float4*)(o_w + (size_t)l * L_O), (uint2*)w_o[l],
            (long long)(L_O / 4));

        qk_rope_w<<<SEQ, 256>>>(pqkv, qknw + (long long)l * QKH * HD, cosb, sinb, pqf, pkf);
        v_transpose_h<<<dim3(SEQ / 32, HD / 32, KVH), dim3(32, 32)>>>(pqkv, pvtf);

        // scores (causal tile skip)
        hgemm<<<dim3(SEQ / 128, SEQ / 128, NH), 256, SMB>>>(
            pqf, HD, pkf, HD, nullptr, pscf, SEQ, HD,
            nullptr, 0,
            (long long)SEQ * HD, (long long)SEQ * HD, (long long)SEQ * SEQ, 1, 1,
            SEQ / 128, nullptr, nullptr, 0);

        softmax_causal_h<<<dim3(SEQ, NH), 256>>>(pscf, maskp, ppf);

        // PV (K-limited)
        hgemm<<<dim3(SEQ / 128, 1, NH), 256, SMB>>>(
            ppf, SEQ, pvtf, SEQ, nullptr, ppaof, HDIM, SEQ,
            nullptr, 0,
            (long long)SEQ * SEQ, (long long)HD * SEQ, (long long)HD, 1, 2,
            1, nullptr, nullptr, 0);

        // O projection + residual (64-row tiles, 256 GEMM CTAs); hosts gu_w[l] (11 conv rows)
        hgemm64<<<dim3(SEQ / 64, HDIM / 128 + 11), 256, SM64>>>(
            ppaof, HDIM, w_o[l], HDIM, px, nullptr, HDIM, HDIM,
            xin, HDIM,
            HDIM / 128, (const float4*)(gu_w + (size_t)l * L_GU), (uint2*)w_gu[l],
            (long long)(L_GU / 4));

        // MLP
        l2norm_rows_h<<<SEQ, 256>>>(px, phnf, HDIM);

        // gate_up GEMM; hosts dn_w[l] (96 GEMM + 15 conv rows)
        hgemm<<<dim3(SEQ / 128, 2 * DFF / 128 + 15, 1), 256, SMB>>>(
            phnf, HDIM, w_gu[l], HDIM, pgu, nullptr, 2 * DFF, HDIM,
            nullptr, 0, 0, 0, 0, 0, 0,
            2 * DFF / 128, (const float4*)(dn_w + (size_t)l * L_DN), (uint2*)w_dn[l],
            (long long)(L_DN / 4));

        silu_mul_h4<<<(SEQ * DFF / 4) / 256, 256>>>((const float4*)pgu, (uint2*)pactf, DFF / 4);

        // down GEMM (64-row tiles); hosts next layer's qkv_w (11 conv rows)
        const int lastL = (l == NLAY - 1);
        hgemm64<<<dim3(SEQ / 64, HDIM / 128 + (lastL ? 0 : 11)), 256, SM64>>>(
            pactf, DFF, w_dn[l], DFF, px, nullptr, HDIM, DFF,
            px, HDIM,
            HDIM / 128,
            lastL ? nullptr : (const float4*)(qkv_w + (size_t)(l + 1) * L_QKV),
            lastL ? nullptr : (uint2*)w_qkv[l + 1],
            lastL ? 0 : (long long)(L_QKV / 4));

        xin = px;
    }

    l2norm_rows<<<1, 256>>>(px + (long long)(SEQ - 1) * HDIM, plast, HDIM);
    lm_head<<<VOC / 8, 256>>>(plast, lm_w, outp);
}

// round 16
// speedup vs baseline: 1.2804x; 1.0509x over previous
#include <cuda_runtime.h>
#include <cuda_fp16.h>
#include <stdint.h>
#include <math.h>

#define SEQ   1024
#define HDIM  2048
#define NH    16
#define KVH   8
#define HD    128
#define QKH   24
#define QKVO  4096
#define DFF   6144
#define VOC   32000
#define NLAY  2

#define L_QKV ((size_t)QKVO * HDIM)
#define L_O   ((size_t)HDIM * HDIM)
#define L_GU  ((size_t)2 * DFF * HDIM)
#define L_DN  ((size_t)HDIM * DFF)
#define L_ALL (L_QKV + L_O + L_GU + L_DN)

// ---------------- device scratch (no allocs allowed) ----------------
__device__ __align__(16) float g_x   [SEQ*HDIM];
__device__ __align__(16) half  g_hnf [SEQ*HDIM];
__device__ __align__(16) half  g_wall[2 * L_ALL];
__device__ __align__(16) half  g_qkvh[SEQ*QKVO];
__device__ __align__(16) half  g_qf  [NH*SEQ*HD];
__device__ __align__(16) half  g_kf  [KVH*SEQ*HD];
__device__ __align__(16) half  g_vtf [KVH*HD*SEQ];
__device__ __align__(16) half  g_scf [NH*SEQ*SEQ];
__device__ __align__(16) half  g_pf  [NH*SEQ*SEQ];
__device__ __align__(16) half  g_paof[SEQ*HDIM];
__device__ __align__(16) half  g_guh [SEQ*2*DFF];
__device__ __align__(16) half  g_actf[SEQ*DFF];
__device__ __align__(16) float g_last[HDIM];

// ---------------- helpers ----------------
__device__ __forceinline__ uint32_t smem_u32(const void* p) {
    uint32_t a;
    asm("{ .reg .u64 t; cvta.to.shared.u64 t, %1; cvt.u32.u64 %0, t; }" : "=r"(a) : "l"(p));
    return a;
}
__device__ __forceinline__ uint32_t pack2h(half a, half b) {
    return (uint32_t)__half_as_ushort(a) | ((uint32_t)__half_as_ushort(b) << 16);
}

#define CPA16(d, s) asm volatile("cp.async.cg.shared.global [%0], [%1], 16;" :: "r"(d), "l"(s))
#define CPA_COMMIT() asm volatile("cp.async.commit_group;" ::: "memory")
#define CPA_WAIT(n)  asm volatile("cp.async.wait_group %0;" :: "n"(n) : "memory")

#define LDSM4(r, a) \
    asm volatile("ldmatrix.sync.aligned.m8n8.x4.shared.b16 {%0,%1,%2,%3}, [%4];" \
        : "=r"((r)[0]), "=r"((r)[1]), "=r"((r)[2]), "=r"((r)[3]) : "r"(a))

#define MMA_F16(c, a, b0, b1) \
    asm volatile("mma.sync.aligned.m16n8k16.row.col.f32.f16.f16.f32 " \
        "{%0,%1,%2,%3}, {%4,%5,%6,%7}, {%8,%9}, {%0,%1,%2,%3};" \
        : "+f"((c)[0]), "+f"((c)[1]), "+f"((c)[2]), "+f"((c)[3]) \
        : "r"((a)[0]), "r"((a)[1]), "r"((a)[2]), "r"((a)[3]), "r"(b0), "r"(b1))

__device__ __forceinline__ uint2 cvt_f4(float4 v) {
    return make_uint2(pack2h(__float2half_rn(v.x), __float2half_rn(v.y)),
                      pack2h(__float2half_rn(v.z), __float2half_rn(v.w)));
}

// MLP=4 grid-stride converter
__device__ __forceinline__ void conv_range(const float4* __restrict__ src,
                                           uint2* __restrict__ dst, long long n4,
                                           long long cb, long long nblk, int tid)
{
    const long long stride = nblk * 256;
    long long i = cb * 256 + tid;
    for (; i + 3 * stride < n4; i += 4 * stride) {
        float4 a = src[i];
        float4 b = src[i + stride];
        float4 c = src[i + 2 * stride];
        float4 d = src[i + 3 * stride];
        dst[i]              = cvt_f4(a);
        dst[i + stride]     = cvt_f4(b);
        dst[i + 2 * stride] = cvt_f4(c);
        dst[i + 3 * stride] = cvt_f4(d);
    }
    for (; i < n4; i += stride) dst[i] = cvt_f4(src[i]);
}

// ============================================================================
// hgemm: 128x128 fp16 GEMM (R13-proven) + hosted converter CTAs (y>=nyG,z==0).
// causal bit0: skip n0>m0 tiles. bit1: K-limit to m0+128.
// ============================================================================
__global__ __launch_bounds__(256, 2)
void hgemm(const half* __restrict__ A, int lda,
           const half* __restrict__ B, int ldb,
           float* __restrict__ Cf, half* __restrict__ Ch, int ldc, int K,
           const float* __restrict__ resid, int ldr,
           long long bsA, long long bsB, long long bsC, int bShiftB, int causal,
           int nyG, const float4* __restrict__ cvsrc, uint2* __restrict__ cvdst,
           long long cvn4)
{
    const int tid = threadIdx.x;

    if ((int)blockIdx.y >= nyG) {
        if (blockIdx.z != 0) return;
        const long long nblk = (long long)gridDim.x * (gridDim.y - nyG);
        const long long cb   = blockIdx.x + (long long)(blockIdx.y - nyG) * gridDim.x;
        conv_range(cvsrc, cvdst, cvn4, cb, nblk, tid);
        return;
    }

    constexpr int STG = 32768;
    extern __shared__ char dynraw[];
    char* sm = (char*)(((uintptr_t)dynraw + 255) & ~(uintptr_t)255);
    const uint32_t smb = smem_u32(sm);

    const int m0 = blockIdx.x * 128;
    const int n0 = blockIdx.y * 128;
    if ((causal & 1) && n0 > m0) return;

    const int lane = tid & 31;
    const int wid  = tid >> 5;
    const int wm   = (wid >> 2) * 64;
    const int wn   = (wid & 3) * 32;

    const long long z = blockIdx.z;
    A += z * bsA;
    B += (z >> bShiftB) * bsB;
    if (Cf) Cf += z * bsC;
    if (Ch) Ch += z * bsC;

    const int Keff = (causal & 2) ? min(K, m0 + 128) : K;
    const int nch  = Keff >> 6;

    const int a_row_l  = lane & 15;
    const int a_colq_l = lane >> 4;
    const int b_row_l  = (lane & 7) + ((lane & 16) >> 1);
    const int b_colq_l = (lane >> 3) & 1;

    float acc[4][4][4];
#pragma unroll
    for (int i = 0; i < 4; i++)
#pragma unroll
        for (int j = 0; j < 4; j++)
#pragma unroll
            for (int q = 0; q < 4; q++) acc[i][j][q] = 0.f;

    auto load_chunk = [&](int c) {
        const int k0 = c << 6;
        const uint32_t st = smb + (c % 3) * STG;
#pragma unroll
        for (int it = 0; it < 8; it++) {
            const int g   = it * 256 + tid;
            const int arr = it >> 2;
            const int r   = (g >> 3) & 127;
            const int q   = g & 7;
            const half* src = arr ? (B + (size_t)(n0 + r) * ldb + k0 + q * 8)
                                  : (A + (size_t)(m0 + r) * lda + k0 + q * 8);
            CPA16(st + arr * 16384 + r * 128 + ((q ^ (r & 7)) << 4), src);
        }
        CPA_COMMIT();
    };

    load_chunk(0);
    if (nch > 1) load_chunk(1);

    for (int c = 0; c < nch; c++) {
        if (c + 1 < nch) CPA_WAIT(1); else CPA_WAIT(0);
        __syncthreads();
        if (c + 2 < nch) load_chunk(c + 2);

        const uint32_t st = smb + (c % 3) * STG;
        const uint32_t sA = st, sB = st + 16384;

#pragma unroll
        for (int kk = 0; kk < 4; kk++) {
            uint32_t af[4][4], bfr[4][2];
            const int acq = kk * 2 + a_colq_l;
#pragma unroll
            for (int mi = 0; mi < 4; mi++) {
                const int r = wm + mi * 16 + a_row_l;
                LDSM4(af[mi], sA + r * 128 + ((acq ^ (r & 7)) << 4));
            }
            const int bcq = kk * 2 + b_colq_l;
#pragma unroll
            for (int nj = 0; nj < 2; nj++) {
                const int r = wn + nj * 16 + b_row_l;
                uint32_t t4[4];
                LDSM4(t4, sB + r * 128 + ((bcq ^ (r & 7)) << 4));
                bfr[nj*2][0] = t4[0]; bfr[nj*2][1] = t4[1];
                bfr[nj*2+1][0] = t4[2]; bfr[nj*2+1][1] = t4[3];
            }
#pragma unroll
            for (int mi = 0; mi < 4; mi++)
#pragma unroll
                for (int ni = 0; ni < 4; ni++)
                    MMA_F16(acc[mi][ni], af[mi], bfr[ni][0], bfr[ni][1]);
        }
    }

    const int g = lane >> 2, t = lane & 3;
#pragma unroll
    for (int mi = 0; mi < 4; mi++)
#pragma unroll
        for (int ni = 0; ni < 4; ni++)
#pragma unroll
            for (int h2 = 0; h2 < 2; h2++) {
                const int row = m0 + wm + mi * 16 + g + h2 * 8;
                const int col = n0 + wn + ni * 8 + 2 * t;
                float v0 = acc[mi][ni][h2 * 2 + 0];
                float v1 = acc[mi][ni][h2 * 2 + 1];
                if (resid) {
                    const float* rp = resid + (size_t)row * ldr + col;
                    v0 += rp[0]; v1 += rp[1];
                }
                if (Cf) *(float2*)(Cf + (size_t)row * ldc + col) = make_float2(v0, v1);
                if (Ch)
                    *(uint32_t*)(Ch + (size_t)row * ldc + col) =
                        pack2h(__float2half_rn(v0), __float2half_rn(v1));
            }
}

// ---------------- standalone fp32 -> fp16 convert (initial qkv-l0) ----------
__global__ void cvt4h(const float4* __restrict__ in, uint2* __restrict__ out, long long n4)
{
    long long i = (long long)blockIdx.x * blockDim.x + threadIdx.x;
    if (i >= n4) return;
    out[i] = cvt_f4(in[i]);
}

// ---------------- row l2norm -> fp16 ----------------
__global__ void l2norm_rows_h(const float* __restrict__ in, half* __restrict__ out, int cols)
{
    const int row = blockIdx.x;
    const float* x = in + (long long)row * cols;
    float s = 0.f;
    for (int c = threadIdx.x; c < cols; c += blockDim.x) { float v = x[c]; s += v * v; }
    __shared__ float red[32];
#pragma unroll
    for (int o = 16; o; o >>= 1) s += __shfl_xor_sync(0xffffffffu, s, o);
    if ((threadIdx.x & 31) == 0) red[threadIdx.x >> 5] = s;
    __syncthreads();
    const int nw = blockDim.x >> 5;
    if (threadIdx.x < 32) {
        float t = (threadIdx.x < nw) ? red[threadIdx.x] : 0.f;
#pragma unroll
        for (int o = 16; o; o >>= 1) t += __shfl_xor_sync(0xffffffffu, t, o);
        if (threadIdx.x == 0) red[0] = rsqrtf(t);
    }
    __syncthreads();
    const float r = red[0];
    for (int c = threadIdx.x; c < cols; c += blockDim.x)
        out[(long long)row * cols + c] = __float2half_rn(x[c] * r);
}

__global__ void l2norm_rows(const float* __restrict__ in, float* __restrict__ out, int cols)
{
    const int row = blockIdx.x;
    const float* x = in + (long long)row * cols;
    float* y = out + (long long)row * cols;
    float s = 0.f;
    for (int c = threadIdx.x; c < cols; c += blockDim.x) { float v = x[c]; s += v * v; }
    __shared__ float red[32];
#pragma unroll
    for (int o = 16; o; o >>= 1) s += __shfl_xor_sync(0xffffffffu, s, o);
    if ((threadIdx.x & 31) == 0) red[threadIdx.x >> 5] = s;
    __syncthreads();
    const int nw = blockDim.x >> 5;
    if (threadIdx.x < 32) {
        float t = (threadIdx.x < nw) ? red[threadIdx.x] : 0.f;
#pragma unroll
        for (int o = 16; o; o >>= 1) t += __shfl_xor_sync(0xffffffffu, t, o);
        if (threadIdx.x == 0) red[0] = rsqrtf(t);
    }
    __syncthreads();
    const float r = red[0];
    for (int c = threadIdx.x; c < cols; c += blockDim.x) y[c] = x[c] * r;
}

// ---------------- warp-per-head norm + RoPE (fp16 in) -> fp16 Q/K ----------
__global__ void qk_rope_w(const half* __restrict__ qkv, const float* __restrict__ qknw,
                          const float* __restrict__ cosb, const float* __restrict__ sinb,
                          half* __restrict__ Q, half* __restrict__ Kb)
{
    const int s    = blockIdx.x;
    const int lane = threadIdx.x & 31;
    const int warp = threadIdx.x >> 5;

#pragma unroll
    for (int hi = 0; hi < 3; hi++) {
        const int h = warp + hi * 8;
        const half* src = qkv + (size_t)s * QKVO + h * HD;
        float v[4];
        float ss = 0.f;
#pragma unroll
        for (int i = 0; i < 4; i++) {
            v[i] = __half2float(src[i * 32 + lane]);
            ss += v[i] * v[i];
        }
#pragma unroll
        for (int o = 16; o; o >>= 1) ss += __shfl_xor_sync(0xffffffffu, ss, o);
        const float r = rsqrtf(ss);
        float nv[4];
#pragma unroll
        for (int i = 0; i < 4; i++)
            nv[i] = v[i] * r * qknw[h * HD + i * 32 + lane];
        half ov[4];
#pragma unroll
        for (int i = 0; i < 4; i++) {
            const int d = i * 32 + lane;
            const float rot = nv[i ^ 2];
            ov[i] = __float2half_rn(nv[i] * cosb[s * HD + d] + rot * sinb[s * HD + d]);
        }
        half* dst = (h < NH) ? (Q + ((size_t)h * SEQ + s) * HD)
                             : (Kb + ((size_t)(h - NH) * SEQ + s) * HD);
#pragma unroll
        for (int i = 0; i < 4; i++) dst[i * 32 + lane] = ov[i];
    }
}

// ---------------- V transpose (fp16 in) -> fp16 ----------------
__global__ void v_transpose_h(const half* __restrict__ qkv, half* __restrict__ Vt)
{
    __shared__ float t[32][33];
    const int h = blockIdx.z;
    const int s0 = blockIdx.x * 32;
    const int d0 = blockIdx.y * 32;
    t[threadIdx.y][threadIdx.x] = __half2float(
        qkv[(size_t)(s0 + threadIdx.y) * QKVO + QKH * HD + h * HD + d0 + threadIdx.x]);
    __syncthreads();
    Vt[((size_t)h * HD + d0 + threadIdx.y) * SEQ + s0 + threadIdx.x] =
        __float2half_rn(t[threadIdx.x][threadIdx.y]);
}

// ---------------- causal softmax (fp16 in/out, K-limited) ----------------
__global__ void softmax_causal_h(const half* __restrict__ scores, const float* __restrict__ maskp,
                                 half* __restrict__ P)
{
    const int q = blockIdx.x;
    const int h = blockIdx.y;
    const int kmax = ((q >> 7) + 1) << 7;
    const half* row = scores + ((size_t)h * SEQ + q) * SEQ;
    const float mpen = -128.f * maskp[0];
    const int tid = threadIdx.x;

    float vals[4];
    float mx = -1e30f;
#pragma unroll
    for (int i = 0; i < 4; i++) {
        int k = tid + i * 256;
        if (k < kmax) {
            float v = __half2float(row[k]) + (k > q ? mpen : 0.f);
            vals[i] = v;
            mx = fmaxf(mx, v);
        } else vals[i] = -1e30f;
    }
    __shared__ float redm[8];
    __shared__ float reds[8];
#pragma unroll
    for (int o = 16; o; o >>= 1) mx = fmaxf(mx, __shfl_xor_sync(0xffffffffu, mx, o));
    if ((tid & 31) == 0) redm[tid >> 5] = mx;
    __syncthreads();
    if (tid < 32) {
        float m2 = (tid < 8) ? redm[tid] : -1e30f;
#pragma unroll
        for (int o = 16; o; o >>= 1) m2 = fmaxf(m2, __shfl_xor_sync(0xffffffffu, m2, o));
        if (tid == 0) redm[0] = m2;
    }
    __syncthreads();
    mx = redm[0];

    float s = 0.f;
#pragma unroll
    for (int i = 0; i < 4; i++) {
        int k = tid + i * 256;
        if (k < kmax) { vals[i] = expf(vals[i] - mx); s += vals[i]; }
    }
#pragma unroll
    for (int o = 16; o; o >>= 1) s += __shfl_xor_sync(0xffffffffu, s, o);
    if ((tid & 31) == 0) reds[tid >> 5] = s;
    __syncthreads();
    if (tid < 32) {
        float t2 = (tid < 8) ? reds[tid] : 0.f;
#pragma unroll
        for (int o = 16; o; o >>= 1) t2 += __shfl_xor_sync(0xffffffffu, t2, o);
        if (tid == 0) reds[0] = 1.f / t2;
    }
    __syncthreads();
    const float inv = reds[0];
    const size_t base = ((size_t)h * SEQ + q) * SEQ;
#pragma unroll
    for (int i = 0; i < 4; i++) {
        int k = tid + i * 256;
        if (k < kmax) P[base + k] = __float2half_rn(vals[i] * inv);
    }
}

// ---------------- SwiGLU (fp16 in, 8-wide) -> fp16 ----------------
__global__ void silu_mul_h8(const uint4* __restrict__ gu, uint4* __restrict__ act, int n8row)
{
    const long long i = (long long)blockIdx.x * blockDim.x + threadIdx.x;  // over SEQ*DFF/8
    const int s  = (int)(i / n8row);
    const int f8 = (int)(i % n8row);
    const uint4 gv = gu[(size_t)s * (2 * n8row) + f8];
    const uint4 uv = gu[(size_t)s * (2 * n8row) + n8row + f8];
    const uint32_t* gp = &gv.x;
    const uint32_t* up = &uv.x;
    uint4 outv;
    uint32_t* op = &outv.x;
#pragma unroll
    for (int j = 0; j < 4; j++) {
        float2 g2 = __half22float2(*(const __half2*)&gp[j]);
        float2 u2 = __half22float2(*(const __half2*)&up[j]);
        float r0 = (g2.x / (1.f + expf(-g2.x))) * u2.x;
        float r1 = (g2.y / (1.f + expf(-g2.y))) * u2.y;
        op[j] = pack2h(__float2half_rn(r0), __float2half_rn(r1));
    }
    act[i] = outv;
}

// ---------------- lm_head GEMV (fp32) ----------------
__global__ void lm_head(const float* __restrict__ last, const float* __restrict__ W,
                        float* __restrict__ out)
{
    const int warp = threadIdx.x >> 5;
    const int lane = threadIdx.x & 31;
    const int v = blockIdx.x * 8 + warp;
    const float* w = W + (long long)v * HDIM;
    float s = 0.f;
#pragma unroll
    for (int j = lane * 4; j < HDIM; j += 128) {
        float4 wv = *(const float4*)(w + j);
        float4 lv = *(const float4*)(last + j);
        s += wv.x * lv.x + wv.y * lv.y + wv.z * lv.z + wv.w * lv.w;
    }
#pragma unroll
    for (int o = 16; o; o >>= 1) s += __shfl_xor_sync(0xffffffffu, s, o);
    if (lane == 0) out[v] = s;
}

// ---------------- launcher ----------------
extern "C" void kernel_launch(void* const* d_in, const int* in_sizes, int n_in,
                              void* d_out, int out_size)
{
    const float* hidden = (const float*)d_in[0];
    const float* qkv_w  = (const float*)d_in[1];
    const float* qknw   = (const float*)d_in[2];
    const float* o_w    = (const float*)d_in[3];
    const float* gu_w   = (const float*)d_in[4];
    const float* dn_w   = (const float*)d_in[5];
    const float* lm_w   = (const float*)d_in[6];
    const float* cosb   = (const float*)d_in[7];
    const float* sinb   = (const float*)d_in[8];
    const float* maskp  = (const float*)d_in[9];
    float* outp = (float*)d_out;

    const int SMB = 3 * 32768 + 256;   // 98560 -> 2 CTAs/SM
    cudaFuncSetAttribute(hgemm, cudaFuncAttributeMaxDynamicSharedMemorySize, SMB);

    float *px, *plast;
    half *phnf, *pwall, *pqkvh, *pqf, *pkf, *pvtf, *pscf, *ppf, *ppaof, *pguh, *pactf;
    cudaGetSymbolAddress((void**)&px,    g_x);
    cudaGetSymbolAddress((void**)&phnf,  g_hnf);
    cudaGetSymbolAddress((void**)&pwall, g_wall);
    cudaGetSymbolAddress((void**)&pqkvh, g_qkvh);
    cudaGetSymbolAddress((void**)&pqf,   g_qf);
    cudaGetSymbolAddress((void**)&pkf,   g_kf);
    cudaGetSymbolAddress((void**)&pvtf,  g_vtf);
    cudaGetSymbolAddress((void**)&pscf,  g_scf);
    cudaGetSymbolAddress((void**)&ppf,   g_pf);
    cudaGetSymbolAddress((void**)&ppaof, g_paof);
    cudaGetSymbolAddress((void**)&pguh,  g_guh);
    cudaGetSymbolAddress((void**)&pactf, g_actf);
    cudaGetSymbolAddress((void**)&plast, g_last);

    half* w_qkv[2]; half* w_o[2]; half* w_gu[2]; half* w_dn[2];
    for (int l = 0; l < 2; l++) {
        half* base = pwall + (size_t)l * L_ALL;
        w_qkv[l] = base;
        w_o[l]   = base + L_QKV;
        w_gu[l]  = base + L_QKV + L_O;
        w_dn[l]  = base + L_QKV + L_O + L_GU;
    }

    // initial serial conversion: qkv weights, layer 0
    {
        long long n4 = (long long)(L_QKV / 4);
        cvt4h<<<(unsigned)((n4 + 255) / 256), 256>>>(
            (const float4*)qkv_w, (uint2*)w_qkv[0], n4);
    }

    const float* xin = hidden;

    for (int l = 0; l < NLAY; l++) {
        l2norm_rows_h<<<SEQ, 256>>>(xin, phnf, HDIM);

        // QKV projection -> fp16; hosts o_w[l] (32 GEMM + 5 conv rows)
        hgemm<<<dim3(SEQ / 128, QKVO / 128 + 5, 1), 256, SMB>>>(
            phnf, HDIM, w_qkv[l], HDIM, nullptr, pqkvh, QKVO, HDIM,
            nullptr, 0, 0, 0, 0, 0, 0,
            QKVO / 128, (const float4*)(o_w + (size_t)l * L_O), (uint2*)w_o[l],
            (long long)(L_O / 4));

        qk_rope_w<<<SEQ, 256>>>(pqkvh, qknw + (long long)l * QKH * HD, cosb, sinb, pqf, pkf);
        v_transpose_h<<<dim3(SEQ / 32, HD / 32, KVH), dim3(32, 32)>>>(pqkvh, pvtf);

        // scores (causal tile skip)
        hgemm<<<dim3(SEQ / 128, SEQ / 128, NH), 256, SMB>>>(
            pqf, HD, pkf, HD, nullptr, pscf, SEQ, HD,
            nullptr, 0,
            (long long)SEQ * HD, (long long)SEQ * HD, (long long)SEQ * SEQ, 1, 1,
            SEQ / 128, nullptr, nullptr, 0);

        softmax_causal_h<<<dim3(SEQ, NH), 256>>>(pscf, maskp, ppf);

        // PV (K-limited)
        hgemm<<<dim3(SEQ / 128, 1, NH), 256, SMB>>>(
            ppf, SEQ, pvtf, SEQ, nullptr, ppaof, HDIM, SEQ,
            nullptr, 0,
            (long long)SEQ * SEQ, (long long)HD * SEQ, (long long)HD, 1, 2,
            1, nullptr, nullptr, 0);

        // O projection + residual; hosts gu_w[l] (16 GEMM + 21 conv)
        hgemm<<<dim3(SEQ / 128, HDIM / 128 + 21, 1), 256, SMB>>>(
            ppaof, HDIM, w_o[l], HDIM, px, nullptr, HDIM, HDIM,
            xin, HDIM, 0, 0, 0, 0, 0,
            HDIM / 128, (const float4*)(gu_w + (size_t)l * L_GU), (uint2*)w_gu[l],
            (long long)(L_GU / 4));

        // MLP
        l2norm_rows_h<<<SEQ, 256>>>(px, phnf, HDIM);

        // gate_up GEMM -> fp16; hosts dn_w[l] (96 GEMM + 15 conv)
        hgemm<<<dim3(SEQ / 128, 2 * DFF / 128 + 15, 1), 256, SMB>>>(
            phnf, HDIM, w_gu[l], HDIM, nullptr, pguh, 2 * DFF, HDIM,
            nullptr, 0, 0, 0, 0, 0, 0,
            2 * DFF / 128, (const float4*)(dn_w + (size_t)l * L_DN), (uint2*)w_dn[l],
            (long long)(L_DN / 4));

        silu_mul_h8<<<(SEQ * DFF / 8) / 256, 256>>>((const uint4*)pguh, (uint4*)pactf, DFF / 8);

        // down GEMM; hosts next layer's qkv_w (16 GEMM + 21 conv)
        const int lastL = (l == NLAY - 1);
        hgemm<<<dim3(SEQ / 128, HDIM / 128 + (lastL ? 0 : 21), 1), 256, SMB>>>(
            pactf, DFF, w_dn[l], DFF, px, nullptr, HDIM, DFF,
            px, HDIM, 0, 0, 0, 0, 0,
            HDIM / 128,
            lastL ? nullptr : (const float4*)(qkv_w + (size_t)(l + 1) * L_QKV),
            lastL ? nullptr : (uint2*)w_qkv[l + 1],
            lastL ? 0 : (long long)(L_QKV / 4));

        xin = px;
    }

    l2norm_rows<<<1, 256>>>(px + (long long)(SEQ - 1) * HDIM, plast, HDIM);
    lm_head<<<VOC / 8, 256>>>(plast, lm_w, outp);
}

// round 17
// speedup vs baseline: 1.3657x; 1.0667x over previous
#include <cuda_runtime.h>
#include <cuda_fp16.h>
#include <stdint.h>
#include <math.h>

#define SEQ   1024
#define HDIM  2048
#define NH    16
#define KVH   8
#define HD    128
#define QKH   24
#define QKVO  4096
#define DFF   6144
#define VOC   32000
#define NLAY  2

#define L_QKV ((size_t)QKVO * HDIM)
#define L_O   ((size_t)HDIM * HDIM)
#define L_GU  ((size_t)2 * DFF * HDIM)
#define L_DN  ((size_t)HDIM * DFF)
#define L_ALL (L_QKV + L_O + L_GU + L_DN)

// ---------------- device scratch (no allocs allowed) ----------------
__device__ __align__(16) float g_x   [SEQ*HDIM];
__device__ __align__(16) half  g_hnf [SEQ*HDIM];
__device__ __align__(16) half  g_wall[2 * L_ALL];
__device__ __align__(16) half  g_qkvh[SEQ*QKVO];
__device__ __align__(16) half  g_qf  [NH*SEQ*HD];
__device__ __align__(16) half  g_kf  [KVH*SEQ*HD];
__device__ __align__(16) half  g_vtf [KVH*HD*SEQ];
__device__ __align__(16) half  g_paof[SEQ*HDIM];
__device__ __align__(16) half  g_guh [SEQ*2*DFF];
__device__ __align__(16) half  g_actf[SEQ*DFF];
__device__ __align__(16) float g_last[HDIM];

// ---------------- helpers ----------------
__device__ __forceinline__ uint32_t smem_u32(const void* p) {
    uint32_t a;
    asm("{ .reg .u64 t; cvta.to.shared.u64 t, %1; cvt.u32.u64 %0, t; }" : "=r"(a) : "l"(p));
    return a;
}
__device__ __forceinline__ uint32_t pack2h(half a, half b) {
    return (uint32_t)__half_as_ushort(a) | ((uint32_t)__half_as_ushort(b) << 16);
}

#define CPA16(d, s) asm volatile("cp.async.cg.shared.global [%0], [%1], 16;" :: "r"(d), "l"(s))
#define CPA_COMMIT() asm volatile("cp.async.commit_group;" ::: "memory")
#define CPA_WAIT(n)  asm volatile("cp.async.wait_group %0;" :: "n"(n) : "memory")

#define LDSM4(r, a) \
    asm volatile("ldmatrix.sync.aligned.m8n8.x4.shared.b16 {%0,%1,%2,%3}, [%4];" \
        : "=r"((r)[0]), "=r"((r)[1]), "=r"((r)[2]), "=r"((r)[3]) : "r"(a))

#define MMA_F16(c, a, b0, b1) \
    asm volatile("mma.sync.aligned.m16n8k16.row.col.f32.f16.f16.f32 " \
        "{%0,%1,%2,%3}, {%4,%5,%6,%7}, {%8,%9}, {%0,%1,%2,%3};" \
        : "+f"((c)[0]), "+f"((c)[1]), "+f"((c)[2]), "+f"((c)[3]) \
        : "r"((a)[0]), "r"((a)[1]), "r"((a)[2]), "r"((a)[3]), "r"(b0), "r"(b1))

__device__ __forceinline__ uint2 cvt_f4(float4 v) {
    return make_uint2(pack2h(__float2half_rn(v.x), __float2half_rn(v.y)),
                      pack2h(__float2half_rn(v.z), __float2half_rn(v.w)));
}

// MLP=4 grid-stride converter
__device__ __forceinline__ void conv_range(const float4* __restrict__ src,
                                           uint2* __restrict__ dst, long long n4,
                                           long long cb, long long nblk, int tid)
{
    const long long stride = nblk * 256;
    long long i = cb * 256 + tid;
    for (; i + 3 * stride < n4; i += 4 * stride) {
        float4 a = src[i];
        float4 b = src[i + stride];
        float4 c = src[i + 2 * stride];
        float4 d = src[i + 3 * stride];
        dst[i]              = cvt_f4(a);
        dst[i + stride]     = cvt_f4(b);
        dst[i + 2 * stride] = cvt_f4(c);
        dst[i + 3 * stride] = cvt_f4(d);
    }
    for (; i < n4; i += stride) dst[i] = cvt_f4(src[i]);
}

// ============================================================================
// hgemm: 128x128 fp16 GEMM (proven) + hosted converter CTAs (y>=nyG, z==0).
// ============================================================================
__global__ __launch_bounds__(256, 2)
void hgemm(const half* __restrict__ A, int lda,
           const half* __restrict__ B, int ldb,
           float* __restrict__ Cf, half* __restrict__ Ch, int ldc, int K,
           const float* __restrict__ resid, int ldr,
           int nyG, const float4* __restrict__ cvsrc, uint2* __restrict__ cvdst,
           long long cvn4)
{
    const int tid = threadIdx.x;

    if ((int)blockIdx.y >= nyG) {
        const long long nblk = (long long)gridDim.x * (gridDim.y - nyG);
        const long long cb   = blockIdx.x + (long long)(blockIdx.y - nyG) * gridDim.x;
        conv_range(cvsrc, cvdst, cvn4, cb, nblk, tid);
        return;
    }

    constexpr int STG = 32768;
    extern __shared__ char dynraw[];
    char* sm = (char*)(((uintptr_t)dynraw + 255) & ~(uintptr_t)255);
    const uint32_t smb = smem_u32(sm);

    const int m0 = blockIdx.x * 128;
    const int n0 = blockIdx.y * 128;

    const int lane = tid & 31;
    const int wid  = tid >> 5;
    const int wm   = (wid >> 2) * 64;
    const int wn   = (wid & 3) * 32;

    const int nch = K >> 6;

    const int a_row_l  = lane & 15;
    const int a_colq_l = lane >> 4;
    const int b_row_l  = (lane & 7) + ((lane & 16) >> 1);
    const int b_colq_l = (lane >> 3) & 1;

    float acc[4][4][4];
#pragma unroll
    for (int i = 0; i < 4; i++)
#pragma unroll
        for (int j = 0; j < 4; j++)
#pragma unroll
            for (int q = 0; q < 4; q++) acc[i][j][q] = 0.f;

    auto load_chunk = [&](int c) {
        const int k0 = c << 6;
        const uint32_t st = smb + (c % 3) * STG;
#pragma unroll
        for (int it = 0; it < 8; it++) {
            const int g   = it * 256 + tid;
            const int arr = it >> 2;
            const int r   = (g >> 3) & 127;
            const int q   = g & 7;
            const half* src = arr ? (B + (size_t)(n0 + r) * ldb + k0 + q * 8)
                                  : (A + (size_t)(m0 + r) * lda + k0 + q * 8);
            CPA16(st + arr * 16384 + r * 128 + ((q ^ (r & 7)) << 4), src);
        }
        CPA_COMMIT();
    };

    load_chunk(0);
    if (nch > 1) load_chunk(1);

    for (int c = 0; c < nch; c++) {
        if (c + 1 < nch) CPA_WAIT(1); else CPA_WAIT(0);
        __syncthreads();
        if (c + 2 < nch) load_chunk(c + 2);

        const uint32_t st = smb + (c % 3) * STG;
        const uint32_t sA = st, sB = st + 16384;

#pragma unroll
        for (int kk = 0; kk < 4; kk++) {
            uint32_t af[4][4], bfr[4][2];
            const int acq = kk * 2 + a_colq_l;
#pragma unroll
            for (int mi = 0; mi < 4; mi++) {
                const int r = wm + mi * 16 + a_row_l;
                LDSM4(af[mi], sA + r * 128 + ((acq ^ (r & 7)) << 4));
            }
            const int bcq = kk * 2 + b_colq_l;
#pragma unroll
            for (int nj = 0; nj < 2; nj++) {
                const int r = wn + nj * 16 + b_row_l;
                uint32_t t4[4];
                LDSM4(t4, sB + r * 128 + ((bcq ^ (r & 7)) << 4));
                bfr[nj*2][0] = t4[0]; bfr[nj*2][1] = t4[1];
                bfr[nj*2+1][0] = t4[2]; bfr[nj*2+1][1] = t4[3];
            }
#pragma unroll
            for (int mi = 0; mi < 4; mi++)
#pragma unroll
                for (int ni = 0; ni < 4; ni++)
                    MMA_F16(acc[mi][ni], af[mi], bfr[ni][0], bfr[ni][1]);
        }
    }

    const int g = lane >> 2, t = lane & 3;
#pragma unroll
    for (int mi = 0; mi < 4; mi++)
#pragma unroll
        for (int ni = 0; ni < 4; ni++)
#pragma unroll
            for (int h2 = 0; h2 < 2; h2++) {
                const int row = m0 + wm + mi * 16 + g + h2 * 8;
                const int col = n0 + wn + ni * 8 + 2 * t;
                float v0 = acc[mi][ni][h2 * 2 + 0];
                float v1 = acc[mi][ni][h2 * 2 + 1];
                if (resid) {
                    const float* rp = resid + (size_t)row * ldr + col;
                    v0 += rp[0]; v1 += rp[1];
                }
                if (Cf) *(float2*)(Cf + (size_t)row * ldc + col) = make_float2(v0, v1);
                if (Ch)
                    *(uint32_t*)(Ch + (size_t)row * ldc + col) =
                        pack2h(__float2half_rn(v0), __float2half_rn(v1));
            }
}

// ============================================================================
// flash_attn: fused scores+softmax+PV. grid=(qb 0..7, head 0..15), 256 thr.
// Each warp owns 16 q-rows. Q resident (32KB); K/V 128-blocks double-buffered.
// Online softmax (fp32 m/l), fp32 O accumulator, fp16 output slab per head.
// ============================================================================
__global__ __launch_bounds__(256, 1)
void flash_attn(const half* __restrict__ Qg, const half* __restrict__ Kg,
                const half* __restrict__ Vtg, const float* __restrict__ maskp,
                half* __restrict__ Oout)
{
    constexpr int TQ = 16384;                 // one 64-k chunk of a 128-row tile
    extern __shared__ char dynraw[];
    char* sm = (char*)(((uintptr_t)dynraw + 255) & ~(uintptr_t)255);
    const uint32_t sQ  = smem_u32(sm);        // 32KB
    const uint32_t sKV = sQ + 32768;          // 2 stages x (K 32KB + V 32KB)

    const int qb  = blockIdx.x;
    const int h   = blockIdx.y;
    const int kvh = h >> 1;
    const int tid = threadIdx.x;
    const int lane = tid & 31;
    const int wid  = tid >> 5;
    const int wq0  = wid * 16;
    const float mpen = -128.f * maskp[0];

    const half* Qp = Qg + ((size_t)h * SEQ + qb * 128) * HD;
    const half* Kp = Kg + (size_t)kvh * SEQ * HD;
    const half* Vp = Vtg + (size_t)kvh * HD * SEQ;

    const int a_row_l  = lane & 15;
    const int a_colq_l = lane >> 4;
    const int b_row_l  = (lane & 7) + ((lane & 16) >> 1);
    const int b_colq_l = (lane >> 3) & 1;
    const int g = lane >> 2, t = lane & 3;

    // load Q (both 64-k chunks)
#pragma unroll
    for (int it = 0; it < 8; it++) {
        const int v = it * 256 + tid;
        const int kc = v >> 10;
        const int r  = (v >> 3) & 127;
        const int q  = v & 7;
        CPA16(sQ + kc * TQ + r * 128 + ((q ^ (r & 7)) << 4),
              Qp + (size_t)r * HD + kc * 64 + q * 8);
    }

    auto load_kv = [&](int kb) {
        const uint32_t st = sKV + (kb & 1) * 65536;
#pragma unroll
        for (int it = 0; it < 8; it++) {
            const int v = it * 256 + tid;
            const int kc = v >> 10;
            const int r  = (v >> 3) & 127;
            const int q  = v & 7;
            CPA16(st + kc * TQ + r * 128 + ((q ^ (r & 7)) << 4),
                  Kp + (size_t)(kb * 128 + r) * HD + kc * 64 + q * 8);
        }
#pragma unroll
        for (int it = 0; it < 8; it++) {
            const int v = it * 256 + tid;
            const int kc = v >> 10;
            const int d  = (v >> 3) & 127;
            const int q  = v & 7;
            CPA16(st + 32768 + kc * TQ + d * 128 + ((q ^ (d & 7)) << 4),
                  Vp + (size_t)d * SEQ + kb * 128 + kc * 64 + q * 8);
        }
        CPA_COMMIT();
    };

    load_kv(0);   // commit covers Q loads too

    float oacc[16][4];
#pragma unroll
    for (int i = 0; i < 16; i++)
#pragma unroll
        for (int q = 0; q < 4; q++) oacc[i][q] = 0.f;
    float m0 = -1e30f, m1 = -1e30f, l0 = 0.f, l1 = 0.f;

    for (int kb = 0; kb <= qb; kb++) {
        CPA_WAIT(0);
        __syncthreads();
        if (kb < qb) load_kv(kb + 1);

        const uint32_t st = sKV + (kb & 1) * 65536;
        const uint32_t sK = st, sV = st + 32768;

        // ---- S = Q K^T (16 x 128 per warp) ----
        float sacc[16][4];
#pragma unroll
        for (int i = 0; i < 16; i++)
#pragma unroll
            for (int q = 0; q < 4; q++) sacc[i][q] = 0.f;

#pragma unroll
        for (int kk = 0; kk < 8; kk++) {
            uint32_t af[4];
            const int rq = wq0 + a_row_l;
            const int acq = (kk & 3) * 2 + a_colq_l;
            LDSM4(af, sQ + (kk >> 2) * TQ + rq * 128 + ((acq ^ (rq & 7)) << 4));
            const int bcq = (kk & 3) * 2 + b_colq_l;
#pragma unroll
            for (int nj = 0; nj < 8; nj++) {
                const int rn = nj * 16 + b_row_l;
                uint32_t t4[4];
                LDSM4(t4, sK + (kk >> 2) * TQ + rn * 128 + ((bcq ^ (rn & 7)) << 4));
                MMA_F16(sacc[nj * 2],     af, t4[0], t4[1]);
                MMA_F16(sacc[nj * 2 + 1], af, t4[2], t4[3]);
            }
        }

        // ---- diagonal-block causal penalty ----
        if (kb == qb) {
            const int r0 = wq0 + g, r1 = r0 + 8;
#pragma unroll
            for (int ni = 0; ni < 16; ni++) {
                const int c0 = ni * 8 + 2 * t, c1 = c0 + 1;
                if (c0 > r0) sacc[ni][0] += mpen;
                if (c1 > r0) sacc[ni][1] += mpen;
                if (c0 > r1) sacc[ni][2] += mpen;
                if (c1 > r1) sacc[ni][3] += mpen;
            }
        }

        // ---- online softmax ----
        float mx0 = -1e30f, mx1 = -1e30f;
#pragma unroll
        for (int ni = 0; ni < 16; ni++) {
            mx0 = fmaxf(mx0, fmaxf(sacc[ni][0], sacc[ni][1]));
            mx1 = fmaxf(mx1, fmaxf(sacc[ni][2], sacc[ni][3]));
        }
#pragma unroll
        for (int o = 1; o <= 2; o <<= 1) {
            mx0 = fmaxf(mx0, __shfl_xor_sync(0xffffffffu, mx0, o));
            mx1 = fmaxf(mx1, __shfl_xor_sync(0xffffffffu, mx1, o));
        }
        const float mn0 = fmaxf(m0, mx0);
        const float mn1 = fmaxf(m1, mx1);
        const float al0 = __expf(m0 - mn0);
        const float al1 = __expf(m1 - mn1);

        float sum0 = 0.f, sum1 = 0.f;
#pragma unroll
        for (int ni = 0; ni < 16; ni++) {
            sacc[ni][0] = __expf(sacc[ni][0] - mn0); sum0 += sacc[ni][0];
            sacc[ni][1] = __expf(sacc[ni][1] - mn0); sum0 += sacc[ni][1];
            sacc[ni][2] = __expf(sacc[ni][2] - mn1); sum1 += sacc[ni][2];
            sacc[ni][3] = __expf(sacc[ni][3] - mn1); sum1 += sacc[ni][3];
        }
#pragma unroll
        for (int o = 1; o <= 2; o <<= 1) {
            sum0 += __shfl_xor_sync(0xffffffffu, sum0, o);
            sum1 += __shfl_xor_sync(0xffffffffu, sum1, o);
        }
        l0 = l0 * al0 + sum0;
        l1 = l1 * al1 + sum1;
        m0 = mn0; m1 = mn1;

#pragma unroll
        for (int ni = 0; ni < 16; ni++) {
            oacc[ni][0] *= al0; oacc[ni][1] *= al0;
            oacc[ni][2] *= al1; oacc[ni][3] *= al1;
        }

        // ---- O += P V^T ----
#pragma unroll
        for (int kt = 0; kt < 8; kt++) {
            uint32_t pa[4];
            pa[0] = pack2h(__float2half_rn(sacc[2*kt][0]),   __float2half_rn(sacc[2*kt][1]));
            pa[1] = pack2h(__float2half_rn(sacc[2*kt][2]),   __float2half_rn(sacc[2*kt][3]));
            pa[2] = pack2h(__float2half_rn(sacc[2*kt+1][0]), __float2half_rn(sacc[2*kt+1][1]));
            pa[3] = pack2h(__float2half_rn(sacc[2*kt+1][2]), __float2half_rn(sacc[2*kt+1][3]));
            const int bcq = (kt & 3) * 2 + b_colq_l;
#pragma unroll
            for (int dn = 0; dn < 8; dn++) {
                const int rd = dn * 16 + b_row_l;
                uint32_t t4[4];
                LDSM4(t4, sV + (kt >> 2) * TQ + rd * 128 + ((bcq ^ (rd & 7)) << 4));
                MMA_F16(oacc[dn * 2],     pa, t4[0], t4[1]);
                MMA_F16(oacc[dn * 2 + 1], pa, t4[2], t4[3]);
            }
        }
        __syncthreads();
    }

    // ---- finalize ----
    const float inv0 = 1.f / l0, inv1 = 1.f / l1;
    const int row0 = qb * 128 + wq0 + g;
    const int row1 = row0 + 8;
#pragma unroll
    for (int ni = 0; ni < 16; ni++) {
        const int col = h * 128 + ni * 8 + 2 * t;
        *(uint32_t*)(Oout + (size_t)row0 * HDIM + col) =
            pack2h(__float2half_rn(oacc[ni][0] * inv0), __float2half_rn(oacc[ni][1] * inv0));
        *(uint32_t*)(Oout + (size_t)row1 * HDIM + col) =
            pack2h(__float2half_rn(oacc[ni][2] * inv1), __float2half_rn(oacc[ni][3] * inv1));
    }
}

// ---------------- standalone fp32 -> fp16 convert (initial qkv-l0) ----------
__global__ void cvt4h(const float4* __restrict__ in, uint2* __restrict__ out, long long n4)
{
    long long i = (long long)blockIdx.x * blockDim.x + threadIdx.x;
    if (i >= n4) return;
    out[i] = cvt_f4(in[i]);
}

// ---------------- row l2norm -> fp16 ----------------
__global__ void l2norm_rows_h(const float* __restrict__ in, half* __restrict__ out, int cols)
{
    const int row = blockIdx.x;
    const float* x = in + (long long)row * cols;
    float s = 0.f;
    for (int c = threadIdx.x; c < cols; c += blockDim.x) { float v = x[c]; s += v * v; }
    __shared__ float red[32];
#pragma unroll
    for (int o = 16; o; o >>= 1) s += __shfl_xor_sync(0xffffffffu, s, o);
    if ((threadIdx.x & 31) == 0) red[threadIdx.x >> 5] = s;
    __syncthreads();
    const int nw = blockDim.x >> 5;
    if (threadIdx.x < 32) {
        float t = (threadIdx.x < nw) ? red[threadIdx.x] : 0.f;
#pragma unroll
        for (int o = 16; o; o >>= 1) t += __shfl_xor_sync(0xffffffffu, t, o);
        if (threadIdx.x == 0) red[0] = rsqrtf(t);
    }
    __syncthreads();
    const float r = red[0];
    for (int c = threadIdx.x; c < cols; c += blockDim.x)
        out[(long long)row * cols + c] = __float2half_rn(x[c] * r);
}

__global__ void l2norm_rows(const float* __restrict__ in, float* __restrict__ out, int cols)
{
    const int row = blockIdx.x;
    const float* x = in + (long long)row * cols;
    float* y = out + (long long)row * cols;
    float s = 0.f;
    for (int c = threadIdx.x; c < cols; c += blockDim.x) { float v = x[c]; s += v * v; }
    __shared__ float red[32];
#pragma unroll
    for (int o = 16; o; o >>= 1) s += __shfl_xor_sync(0xffffffffu, s, o);
    if ((threadIdx.x & 31) == 0) red[threadIdx.x >> 5] = s;
    __syncthreads();
    const int nw = blockDim.x >> 5;
    if (threadIdx.x < 32) {
        float t = (threadIdx.x < nw) ? red[threadIdx.x] : 0.f;
#pragma unroll
        for (int o = 16; o; o >>= 1) t += __shfl_xor_sync(0xffffffffu, t, o);
        if (threadIdx.x == 0) red[0] = rsqrtf(t);
    }
    __syncthreads();
    const float r = red[0];
    for (int c = threadIdx.x; c < cols; c += blockDim.x) y[c] = x[c] * r;
}

// ---------------- warp-per-head norm + RoPE (fp16 in) -> fp16 Q/K ----------
__global__ void qk_rope_w(const half* __restrict__ qkv, const float* __restrict__ qknw,
                          const float* __restrict__ cosb, const float* __restrict__ sinb,
                          half* __restrict__ Q, half* __restrict__ Kb)
{
    const int s    = blockIdx.x;
    const int lane = threadIdx.x & 31;
    const int warp = threadIdx.x >> 5;

#pragma unroll
    for (int hi = 0; hi < 3; hi++) {
        const int h = warp + hi * 8;
        const half* src = qkv + (size_t)s * QKVO + h * HD;
        float v[4];
        float ss = 0.f;
#pragma unroll
        for (int i = 0; i < 4; i++) {
            v[i] = __half2float(src[i * 32 + lane]);
            ss += v[i] * v[i];
        }
#pragma unroll
        for (int o = 16; o; o >>= 1) ss += __shfl_xor_sync(0xffffffffu, ss, o);
        const float r = rsqrtf(ss);
        float nv[4];
#pragma unroll
        for (int i = 0; i < 4; i++)
            nv[i] = v[i] * r * qknw[h * HD + i * 32 + lane];
        half ov[4];
#pragma unroll
        for (int i = 0; i < 4; i++) {
            const int d = i * 32 + lane;
            const float rot = nv[i ^ 2];
            ov[i] = __float2half_rn(nv[i] * cosb[s * HD + d] + rot * sinb[s * HD + d]);
        }
        half* dst = (h < NH) ? (Q + ((size_t)h * SEQ + s) * HD)
                             : (Kb + ((size_t)(h - NH) * SEQ + s) * HD);
#pragma unroll
        for (int i = 0; i < 4; i++) dst[i * 32 + lane] = ov[i];
    }
}

// ---------------- V transpose (fp16 in) -> fp16 ----------------
__global__ void v_transpose_h(const half* __restrict__ qkv, half* __restrict__ Vt)
{
    __shared__ float t[32][33];
    const int h = blockIdx.z;
    const int s0 = blockIdx.x * 32;
    const int d0 = blockIdx.y * 32;
    t[threadIdx.y][threadIdx.x] = __half2float(
        qkv[(size_t)(s0 + threadIdx.y) * QKVO + QKH * HD + h * HD + d0 + threadIdx.x]);
    __syncthreads();
    Vt[((size_t)h * HD + d0 + threadIdx.y) * SEQ + s0 + threadIdx.x] =
        __float2half_rn(t[threadIdx.x][threadIdx.y]);
}

// ---------------- SwiGLU (fp16 in, 8-wide) -> fp16 ----------------
__global__ void silu_mul_h8(const uint4* __restrict__ gu, uint4* __restrict__ act, int n8row)
{
    const long long i = (long long)blockIdx.x * blockDim.x + threadIdx.x;
    const int s  = (int)(i / n8row);
    const int f8 = (int)(i % n8row);
    const uint4 gv = gu[(size_t)s * (2 * n8row) + f8];
    const uint4 uv = gu[(size_t)s * (2 * n8row) + n8row + f8];
    const uint32_t* gp = &gv.x;
    const uint32_t* up = &uv.x;
    uint4 outv;
    uint32_t* op = &outv.x;
#pragma unroll
    for (int j = 0; j < 4; j++) {
        float2 g2 = __half22float2(*(const __half2*)&gp[j]);
        float2 u2 = __half22float2(*(const __half2*)&up[j]);
        float r0 = (g2.x / (1.f + expf(-g2.x))) * u2.x;
        float r1 = (g2.y / (1.f + expf(-g2.y))) * u2.y;
        op[j] = pack2h(__float2half_rn(r0), __float2half_rn(r1));
    }
    act[i] = outv;
}

// ---------------- lm_head GEMV (fp32) ----------------
__global__ void lm_head(const float* __restrict__ last, const float* __restrict__ W,
                        float* __restrict__ out)
{
    const int warp = threadIdx.x >> 5;
    const int lane = threadIdx.x & 31;
    const int v = blockIdx.x * 8 + warp;
    const float* w = W + (long long)v * HDIM;
    float s = 0.f;
#pragma unroll
    for (int j = lane * 4; j < HDIM; j += 128) {
        float4 wv = *(const float4*)(w + j);
        float4 lv = *(const float4*)(last + j);
        s += wv.x * lv.x + wv.y * lv.y + wv.z * lv.z + wv.w * lv.w;
    }
#pragma unroll
    for (int o = 16; o; o >>= 1) s += __shfl_xor_sync(0xffffffffu, s, o);
    if (lane == 0) out[v] = s;
}

// ---------------- launcher ----------------
extern "C" void kernel_launch(void* const* d_in, const int* in_sizes, int n_in,
                              void* d_out, int out_size)
{
    const float* hidden = (const float*)d_in[0];
    const float* qkv_w  = (const float*)d_in[1];
    const float* qknw   = (const float*)d_in[2];
    const float* o_w    = (const float*)d_in[3];
    const float* gu_w   = (const float*)d_in[4];
    const float* dn_w   = (const float*)d_in[5];
    const float* lm_w   = (const float*)d_in[6];
    const float* cosb   = (const float*)d_in[7];
    const float* sinb   = (const float*)d_in[8];
    const float* maskp  = (const float*)d_in[9];
    float* outp = (float*)d_out;

    const int SMB = 3 * 32768 + 256;           // hgemm: 2 CTAs/SM
    const int SMF = 32768 + 2 * 65536 + 256;   // flash: 163,840+pad, 1 CTA/SM
    cudaFuncSetAttribute(hgemm,      cudaFuncAttributeMaxDynamicSharedMemorySize, SMB);
    cudaFuncSetAttribute(flash_attn, cudaFuncAttributeMaxDynamicSharedMemorySize, SMF);

    float *px, *plast;
    half *phnf, *pwall, *pqkvh, *pqf, *pkf, *pvtf, *ppaof, *pguh, *pactf;
    cudaGetSymbolAddress((void**)&px,    g_x);
    cudaGetSymbolAddress((void**)&phnf,  g_hnf);
    cudaGetSymbolAddress((void**)&pwall, g_wall);
    cudaGetSymbolAddress((void**)&pqkvh, g_qkvh);
    cudaGetSymbolAddress((void**)&pqf,   g_qf);
    cudaGetSymbolAddress((void**)&pkf,   g_kf);
    cudaGetSymbolAddress((void**)&pvtf,  g_vtf);
    cudaGetSymbolAddress((void**)&ppaof, g_paof);
    cudaGetSymbolAddress((void**)&pguh,  g_guh);
    cudaGetSymbolAddress((void**)&pactf, g_actf);
    cudaGetSymbolAddress((void**)&plast, g_last);

    half* w_qkv[2]; half* w_o[2]; half* w_gu[2]; half* w_dn[2];
    for (int l = 0; l < 2; l++) {
        half* base = pwall + (size_t)l * L_ALL;
        w_qkv[l] = base;
        w_o[l]   = base + L_QKV;
        w_gu[l]  = base + L_QKV + L_O;
        w_dn[l]  = base + L_QKV + L_O + L_GU;
    }

    // initial serial conversion: qkv weights, layer 0
    {
        long long n4 = (long long)(L_QKV / 4);
        cvt4h<<<(unsigned)((n4 + 255) / 256), 256>>>(
            (const float4*)qkv_w, (uint2*)w_qkv[0], n4);
    }

    const float* xin = hidden;

    for (int l = 0; l < NLAY; l++) {
        l2norm_rows_h<<<SEQ, 256>>>(xin, phnf, HDIM);

        // QKV projection -> fp16; hosts o_w[l] (32 GEMM + 5 conv rows)
        hgemm<<<dim3(SEQ / 128, QKVO / 128 + 5), 256, SMB>>>(
            phnf, HDIM, w_qkv[l], HDIM, nullptr, pqkvh, QKVO, HDIM,
            nullptr, 0,
            QKVO / 128, (const float4*)(o_w + (size_t)l * L_O), (uint2*)w_o[l],
            (long long)(L_O / 4));

        qk_rope_w<<<SEQ, 256>>>(pqkvh, qknw + (long long)l * QKH * HD, cosb, sinb, pqf, pkf);
        v_transpose_h<<<dim3(SEQ / 32, HD / 32, KVH), dim3(32, 32)>>>(pqkvh, pvtf);

        // fused attention
        flash_attn<<<dim3(SEQ / 128, NH), 256, SMF>>>(pqf, pkf, pvtf, maskp, ppaof);

        // O projection + residual; hosts gu_w[l] (16 GEMM + 21 conv)
        hgemm<<<dim3(SEQ / 128, HDIM / 128 + 21), 256, SMB>>>(
            ppaof, HDIM, w_o[l], HDIM, px, nullptr, HDIM, HDIM,
            xin, HDIM,
            HDIM / 128, (const float4*)(gu_w + (size_t)l * L_GU), (uint2*)w_gu[l],
            (long long)(L_GU / 4));

        // MLP
        l2norm_rows_h<<<SEQ, 256>>>(px, phnf, HDIM);

        // gate_up GEMM -> fp16; hosts dn_w[l] (96 GEMM + 15 conv)
        hgemm<<<dim3(SEQ / 128, 2 * DFF / 128 + 15), 256, SMB>>>(
            phnf, HDIM, w_gu[l], HDIM, nullptr, pguh, 2 * DFF, HDIM,
            nullptr, 0,
            2 * DFF / 128, (const float4*)(dn_w + (size_t)l * L_DN), (uint2*)w_dn[l],
            (long long)(L_DN / 4));

        silu_mul_h8<<<(SEQ * DFF / 8) / 256, 256>>>((const uint4*)pguh, (uint4*)pactf, DFF / 8);

        // down GEMM; hosts next layer's qkv_w (16 GEMM + 21 conv)
        const int lastL = (l == NLAY - 1);
        hgemm<<<dim3(SEQ / 128, HDIM / 128 + (lastL ? 0 : 21)), 256, SMB>>>(
            pactf, DFF, w_dn[l], DFF, px, nullptr, HDIM, DFF,
            px, HDIM,
            HDIM / 128,
            lastL ? nullptr : (const float4*)(qkv_w + (size_t)(l + 1) * L_QKV),
            lastL ? nullptr : (uint2*)w_qkv[l + 1],
            lastL ? 0 : (long long)(L_QKV / 4));

        xin = px;
    }

    l2norm_rows<<<1, 256>>>(px + (long long)(SEQ - 1) * HDIM, plast, HDIM);
    lm_head<<<VOC / 8, 256>>>(plast, lm_w, outp);
}